// round 11
// baseline (speedup 1.0000x reference)
#include <cuda_runtime.h>
#include <cuda_bf16.h>
#include <cstdint>
#include <math.h>

#define S_LEN 2048
#define BATCH 4
#define EMB   1024
#define NH    16
#define HD    64
#define NTOK  (BATCH * S_LEN)   // 8192

// ---------------- scratch (device globals; no allocs allowed) --------------
__device__ __nv_bfloat16 g_xh[NTOK * EMB];
__device__ __nv_bfloat16 g_xl[NTOK * EMB];
__device__ __nv_bfloat16 g_wh[4][EMB * EMB];
__device__ __nv_bfloat16 g_wl[4][EMB * EMB];
__device__ __nv_bfloat16 g_Qh[NTOK * EMB];
__device__ __nv_bfloat16 g_Ql[NTOK * EMB];
__device__ __nv_bfloat16 g_Kh[NTOK * EMB];
__device__ __nv_bfloat16 g_Kl[NTOK * EMB];
__device__ __nv_bfloat16 g_Vh[NTOK * EMB];
__device__ __nv_bfloat16 g_Vl[NTOK * EMB];
__device__ __nv_bfloat16 g_Oh[NTOK * EMB];
__device__ __nv_bfloat16 g_Ol[NTOK * EMB];

// ---------------- helpers --------------------------------------------------
__device__ __forceinline__ uint32_t smem_u32(const void* p) {
    uint32_t a;
    asm("{ .reg .u64 t; cvta.to.shared.u64 t, %1; cvt.u32.u64 %0, t; }" : "=r"(a) : "l"(p));
    return a;
}
__device__ __forceinline__ void ldsm_x4(uint32_t a, uint32_t& r0, uint32_t& r1,
                                        uint32_t& r2, uint32_t& r3) {
    asm volatile("ldmatrix.sync.aligned.m8n8.x4.shared.b16 {%0,%1,%2,%3}, [%4];"
                 : "=r"(r0), "=r"(r1), "=r"(r2), "=r"(r3) : "r"(a));
}
__device__ __forceinline__ void ldsm_x4t(uint32_t a, uint32_t& r0, uint32_t& r1,
                                         uint32_t& r2, uint32_t& r3) {
    asm volatile("ldmatrix.sync.aligned.m8n8.x4.trans.shared.b16 {%0,%1,%2,%3}, [%4];"
                 : "=r"(r0), "=r"(r1), "=r"(r2), "=r"(r3) : "r"(a));
}
__device__ __forceinline__ void mma_bf16(float* d, const uint32_t* a,
                                         uint32_t b0, uint32_t b1) {
    asm volatile(
        "mma.sync.aligned.m16n8k16.row.col.f32.bf16.bf16.f32 "
        "{%0,%1,%2,%3}, {%4,%5,%6,%7}, {%8,%9}, {%0,%1,%2,%3};"
        : "+f"(d[0]), "+f"(d[1]), "+f"(d[2]), "+f"(d[3])
        : "r"(a[0]), "r"(a[1]), "r"(a[2]), "r"(a[3]), "r"(b0), "r"(b1));
}
__device__ __forceinline__ void split2(float x, float y, uint32_t& hi, uint32_t& lo) {
    __nv_bfloat162 h = __floats2bfloat162_rn(x, y);
    hi = *(uint32_t*)&h;
    __nv_bfloat162 l = __floats2bfloat162_rn(x - __bfloat162float(h.x),
                                             y - __bfloat162float(h.y));
    lo = *(uint32_t*)&l;
}
#define CP_ASYNC16(s, g) \
    asm volatile("cp.async.cg.shared.global [%0], [%1], 16;" :: "r"(s), "l"(g) : "memory")
#define CP_COMMIT() asm volatile("cp.async.commit_group;" ::: "memory")
#define CP_WAIT0()  asm volatile("cp.async.wait_group 0;" ::: "memory")

// ---------------------------------------------------------------------------
// split fp32 -> (hi, lo) bf16
// ---------------------------------------------------------------------------
__global__ __launch_bounds__(256) void split_k(
    const float* __restrict__ src, __nv_bfloat16* __restrict__ hi,
    __nv_bfloat16* __restrict__ lo, int n4)
{
    int i = blockIdx.x * 256 + threadIdx.x;
    if (i >= n4) return;
    float4 v = ((const float4*)src)[i];
    float x[4] = {v.x, v.y, v.z, v.w};
    __nv_bfloat16 h[4], l[4];
    #pragma unroll
    for (int j = 0; j < 4; j++) {
        h[j] = __float2bfloat16_rn(x[j]);
        l[j] = __float2bfloat16_rn(x[j] - __bfloat162float(h[j]));
    }
    ((uint2*)hi)[i] = *(uint2*)h;
    ((uint2*)lo)[i] = *(uint2*)l;
}

// ---------------------------------------------------------------------------
// mma.sync split-bf16 GEMM: C = A @ W_z^T.  CTA tile 128x256, warp tile 64x64
// (8 warps, 2m x 4n), K chunk 64, 2-stage cp.async, one barrier per chunk.
// ---------------------------------------------------------------------------
#define GP 72
#define GA_H (128 * GP)                 // 9216 halves
#define GB_H (256 * GP)                 // 18432 halves
#define GSTAGE_H (2 * GA_H + 2 * GB_H)  // 55296 halves
#define GEMM_SMEM (2 * GSTAGE_H * 2)    // 221184 bytes

__global__ __launch_bounds__(256, 1) void gemm_tc(
    const __nv_bfloat16* __restrict__ Ah, const __nv_bfloat16* __restrict__ Al,
    const __nv_bfloat16* __restrict__ WhB, const __nv_bfloat16* __restrict__ WlB,
    float* __restrict__ Cf,
    __nv_bfloat16* __restrict__ C0h, __nv_bfloat16* __restrict__ C0l,
    __nv_bfloat16* __restrict__ C1h, __nv_bfloat16* __restrict__ C1l,
    __nv_bfloat16* __restrict__ C2h, __nv_bfloat16* __restrict__ C2l)
{
    extern __shared__ __nv_bfloat16 sm[];
    const uint32_t sb = smem_u32(sm);
    const int tid = threadIdx.x, lane = tid & 31, w = tid >> 5;
    const int wm = w & 1, wn = w >> 1;          // 2m x 4n warp grid
    const int m0 = blockIdx.y * 128, n0 = blockIdx.x * 256;
    const int z = blockIdx.z;
    const __nv_bfloat16* Bh = WhB + (size_t)z * EMB * EMB;
    const __nv_bfloat16* Bl = WlB + (size_t)z * EMB * EMB;
    __nv_bfloat16* Ch = (z == 0) ? C0h : (z == 1) ? C1h : C2h;
    __nv_bfloat16* Cl = (z == 0) ? C0l : (z == 1) ? C1l : C2l;

    const __nv_bfloat16* srcs[4] = {Ah, Al, Bh, Bl};

    auto issue = [&](int k0, int st) {
        #pragma unroll
        for (int i = 0; i < 24; i++) {
            int idx = i * 256 + tid;              // 0..6143 (16B chunks)
            int t, rel, smoff, r0;
            if (idx < 2048) {                     // A tiles: 2 x 1024 chunks
                t = idx >> 10; rel = idx & 1023;
                smoff = t * GA_H; r0 = m0;
            } else {                              // B tiles: 2 x 2048 chunks
                int x2 = idx - 2048;
                t = 2 + (x2 >> 11); rel = x2 & 2047;
                smoff = 2 * GA_H + (t - 2) * GB_H; r0 = n0;
            }
            int row = rel >> 3, c8 = (rel & 7) * 8;
            const __nv_bfloat16* g = srcs[t] + (size_t)(r0 + row) * EMB + k0 + c8;
            uint32_t s = sb + (uint32_t)(st * GSTAGE_H + smoff + row * GP + c8) * 2;
            CP_ASYNC16(s, g);
        }
        CP_COMMIT();
    };

    issue(0, 0);
    float acc[4][8][4] = {};

    for (int c = 0; c < 16; c++) {
        const int st = c & 1;
        CP_WAIT0();
        __syncthreads();
        if (c + 1 < 16) issue((c + 1) * 64, st ^ 1);

        const uint32_t abase = sb + (uint32_t)(st * GSTAGE_H) * 2;
        const uint32_t bbase = sb + (uint32_t)(st * GSTAGE_H + 2 * GA_H) * 2;
        #pragma unroll
        for (int kc = 0; kc < 4; kc++) {
            uint32_t af[4][4], alf[4][4], bf[4][4], blf[4][4];
            #pragma unroll
            for (int mt = 0; mt < 4; mt++) {
                int row = wm * 64 + mt * 16 + (lane & 15);
                uint32_t a = abase + (row * GP + kc * 16 + 8 * (lane >> 4)) * 2;
                ldsm_x4(a, af[mt][0], af[mt][1], af[mt][2], af[mt][3]);
                ldsm_x4(a + GA_H * 2, alf[mt][0], alf[mt][1], alf[mt][2], alf[mt][3]);
            }
            #pragma unroll
            for (int g = 0; g < 4; g++) {
                int row = wn * 64 + g * 16 + (lane & 7) + 8 * ((lane >> 3) & 1);
                uint32_t b = bbase + (row * GP + kc * 16 + 8 * (lane >> 4)) * 2;
                ldsm_x4(b, bf[g][0], bf[g][1], bf[g][2], bf[g][3]);
                ldsm_x4(b + GB_H * 2, blf[g][0], blf[g][1], blf[g][2], blf[g][3]);
            }
            #pragma unroll
            for (int mt = 0; mt < 4; mt++)
                #pragma unroll
                for (int g = 0; g < 4; g++) {
                    mma_bf16(acc[mt][2*g],   af[mt],  bf[g][0],  bf[g][2]);
                    mma_bf16(acc[mt][2*g],   af[mt],  blf[g][0], blf[g][2]);
                    mma_bf16(acc[mt][2*g],   alf[mt], bf[g][0],  bf[g][2]);
                    mma_bf16(acc[mt][2*g+1], af[mt],  bf[g][1],  bf[g][3]);
                    mma_bf16(acc[mt][2*g+1], af[mt],  blf[g][1], blf[g][3]);
                    mma_bf16(acc[mt][2*g+1], alf[mt], bf[g][1],  bf[g][3]);
                }
        }
        __syncthreads();
    }

    #pragma unroll
    for (int mt = 0; mt < 4; mt++) {
        int grow = m0 + wm * 64 + mt * 16 + (lane >> 2);
        #pragma unroll
        for (int nt = 0; nt < 8; nt++) {
            int gcol = n0 + wn * 64 + nt * 8 + 2 * (lane & 3);
            float* a = acc[mt][nt];
            if (Cf) {
                *(float2*)(Cf + (size_t)grow * EMB + gcol) = make_float2(a[0], a[1]);
                *(float2*)(Cf + (size_t)(grow + 8) * EMB + gcol) = make_float2(a[2], a[3]);
            } else {
                uint32_t h, l;
                split2(a[0], a[1], h, l);
                *(uint32_t*)(Ch + (size_t)grow * EMB + gcol) = h;
                *(uint32_t*)(Cl + (size_t)grow * EMB + gcol) = l;
                split2(a[2], a[3], h, l);
                *(uint32_t*)(Ch + (size_t)(grow + 8) * EMB + gcol) = h;
                *(uint32_t*)(Cl + (size_t)(grow + 8) * EMB + gcol) = l;
            }
        }
    }
}

// ---------------------------------------------------------------------------
// Flash attention, mma.sync split-bf16.  CTA = 256 q-rows, 8 warps x 32 rows
// (2 m16 tiles per warp -> V/K fragment reuse), cp.async 2-stage K/V pipeline,
// qt-descending remap, per-warp masked-tile skip.
// ---------------------------------------------------------------------------
#define FPH 72
#define FQ_H (256 * FPH)              // 18432 halves per (h|l)
#define FK_H (64 * FPH)               // 4608 halves
#define FSTG_H (4 * FK_H)             // 18432 halves per stage
#define FLASH_SMEM ((2 * FQ_H + 2 * FSTG_H) * 2 + 2 * 64 * 4)   // 147968 B

__global__ __launch_bounds__(256, 1) void flash_tc(
    const __nv_bfloat16* __restrict__ Qh, const __nv_bfloat16* __restrict__ Ql,
    const __nv_bfloat16* __restrict__ Kh, const __nv_bfloat16* __restrict__ Kl,
    const __nv_bfloat16* __restrict__ Vh, const __nv_bfloat16* __restrict__ Vl,
    const int* __restrict__ am,
    __nv_bfloat16* __restrict__ Oh, __nv_bfloat16* __restrict__ Ol)
{
    extern __shared__ __nv_bfloat16 sm[];
    const uint32_t sb = smem_u32(sm);
    int* ambuf = (int*)(sm + 2 * FQ_H + 2 * FSTG_H);

    const int tid = threadIdx.x, lane = tid & 31, w = tid >> 5;
    const int qt = (int)(gridDim.x - 1 - blockIdx.x);   // heavy tiles first
    const int q0 = qt * 256;
    const size_t rowbase = (size_t)blockIdx.z * S_LEN;
    const int colbase = blockIdx.y * HD;

    const __nv_bfloat16* srcs[4] = {Kh, Kl, Vh, Vl};

    auto prefetch = [&](int kt, int st) {
        const int k0 = kt * 64;
        #pragma unroll
        for (int i = 0; i < 8; i++) {
            int idx = i * 256 + tid;
            int t = idx >> 9, j = idx & 511;
            int row = j >> 3, c8 = (j & 7) * 8;
            const __nv_bfloat16* g = srcs[t] + (rowbase + k0 + row) * EMB + colbase + c8;
            uint32_t s = sb + (uint32_t)(2 * FQ_H + st * FSTG_H + t * FK_H + row * FPH + c8) * 2;
            CP_ASYNC16(s, g);
        }
        if (tid < 16) {
            const int* g = am + rowbase + k0 + tid * 4;
            uint32_t s = sb + (uint32_t)(2 * FQ_H + 2 * FSTG_H) * 2 + (st * 64 + tid * 4) * 4;
            CP_ASYNC16(s, g);
        }
        CP_COMMIT();
    };

    // Q tile (hi + lo), 256 rows
    #pragma unroll
    for (int i = 0; i < 16; i++) {
        int idx = i * 256 + tid;              // 0..4095
        int mtx = idx >> 11, j = idx & 2047;
        int row = j >> 3, c8 = (j & 7) * 8;
        size_t go = (rowbase + q0 + row) * EMB + colbase + c8;
        const __nv_bfloat16* g = mtx ? Ql : Qh;
        *(float4*)&sm[mtx * FQ_H + row * FPH + c8] = *(const float4*)&g[go];
    }
    prefetch(0, 0);

    float oacc[2][8][4] = {};
    float mr[2][2] = {{-1e30f, -1e30f}, {-1e30f, -1e30f}};
    float lr[2][2] = {};

    const uint32_t aQh = sb, aQl = sb + FQ_H * 2;
    const int wrow0 = q0 + w * 32;            // first q-row of this warp
    const int nkt = 4 * qt + 4;

    for (int kt = 0; kt < nkt; kt++) {
        const int k0 = kt * 64;
        const int st = kt & 1;
        CP_WAIT0();
        __syncthreads();
        if (kt + 1 < nkt) prefetch(kt + 1, st ^ 1);

        if (k0 > wrow0 + 31) continue;        // fully masked for this warp

        const uint32_t aKh = sb + (uint32_t)(2 * FQ_H + st * FSTG_H) * 2;
        const uint32_t aKl = aKh + FK_H * 2;
        const uint32_t aVh = aKl + FK_H * 2;
        const uint32_t aVl = aVh + FK_H * 2;
        const int* amb = ambuf + st * 64;

        // ---- S = Q @ K^T (3-term split), both m-tiles share K frags ----
        float sacc[2][8][4] = {};
        #pragma unroll
        for (int kc = 0; kc < 4; kc++) {
            uint32_t qa[2][4], qla[2][4];
            #pragma unroll
            for (int mt = 0; mt < 2; mt++) {
                int row = w * 32 + mt * 16 + (lane & 15);
                uint32_t a = (row * FPH + kc * 16 + 8 * (lane >> 4)) * 2;
                ldsm_x4(aQh + a, qa[mt][0], qa[mt][1], qa[mt][2], qa[mt][3]);
                ldsm_x4(aQl + a, qla[mt][0], qla[mt][1], qla[mt][2], qla[mt][3]);
            }
            #pragma unroll
            for (int np = 0; np < 4; np++) {
                int row = np * 16 + (lane & 7) + 8 * ((lane >> 3) & 1);
                uint32_t boff = (row * FPH + kc * 16 + 8 * (lane >> 4)) * 2;
                uint32_t kh[4], kl[4];
                ldsm_x4(aKh + boff, kh[0], kh[1], kh[2], kh[3]);
                ldsm_x4(aKl + boff, kl[0], kl[1], kl[2], kl[3]);
                #pragma unroll
                for (int mt = 0; mt < 2; mt++) {
                    mma_bf16(sacc[mt][2*np],   qa[mt],  kh[0], kh[2]);
                    mma_bf16(sacc[mt][2*np],   qa[mt],  kl[0], kl[2]);
                    mma_bf16(sacc[mt][2*np],   qla[mt], kh[0], kh[2]);
                    mma_bf16(sacc[mt][2*np+1], qa[mt],  kh[1], kh[3]);
                    mma_bf16(sacc[mt][2*np+1], qa[mt],  kl[1], kl[3]);
                    mma_bf16(sacc[mt][2*np+1], qla[mt], kh[1], kh[3]);
                }
            }
        }

        // ---- online softmax in fragments (per m-tile) ----
        #pragma unroll
        for (int mt = 0; mt < 2; mt++) {
            const int qrow = wrow0 + mt * 16 + (lane >> 2);
            const bool needmask = (k0 + 63) > (wrow0 + mt * 16);
            float mx0 = -1e30f, mx1 = -1e30f;
            #pragma unroll
            for (int t = 0; t < 8; t++) {
                int lc = t * 8 + 2 * (lane & 3);
                int a0 = amb[lc], a1 = amb[lc + 1];
                float s0 = a0 ? sacc[mt][t][0] * 0.125f : -1e30f;
                float s1 = a1 ? sacc[mt][t][1] * 0.125f : -1e30f;
                float s2 = a0 ? sacc[mt][t][2] * 0.125f : -1e30f;
                float s3 = a1 ? sacc[mt][t][3] * 0.125f : -1e30f;
                if (needmask) {
                    int cg = k0 + lc;
                    if (cg > qrow)         s0 = -1e30f;
                    if (cg + 1 > qrow)     s1 = -1e30f;
                    if (cg > qrow + 8)     s2 = -1e30f;
                    if (cg + 1 > qrow + 8) s3 = -1e30f;
                }
                sacc[mt][t][0] = s0; sacc[mt][t][1] = s1;
                sacc[mt][t][2] = s2; sacc[mt][t][3] = s3;
                mx0 = fmaxf(mx0, fmaxf(s0, s1));
                mx1 = fmaxf(mx1, fmaxf(s2, s3));
            }
            mx0 = fmaxf(mx0, __shfl_xor_sync(0xffffffffu, mx0, 1));
            mx0 = fmaxf(mx0, __shfl_xor_sync(0xffffffffu, mx0, 2));
            mx1 = fmaxf(mx1, __shfl_xor_sync(0xffffffffu, mx1, 1));
            mx1 = fmaxf(mx1, __shfl_xor_sync(0xffffffffu, mx1, 2));
            float mn0 = fmaxf(mr[mt][0], mx0), mn1 = fmaxf(mr[mt][1], mx1);
            float al0 = __expf(mr[mt][0] - mn0), al1 = __expf(mr[mt][1] - mn1);
            mr[mt][0] = mn0; mr[mt][1] = mn1;
            float sm0 = 0.f, sm1 = 0.f;
            #pragma unroll
            for (int t = 0; t < 8; t++) {
                float p0 = __expf(sacc[mt][t][0] - mn0);
                float p1 = __expf(sacc[mt][t][1] - mn0);
                float p2 = __expf(sacc[mt][t][2] - mn1);
                float p3 = __expf(sacc[mt][t][3] - mn1);
                sacc[mt][t][0] = p0; sacc[mt][t][1] = p1;
                sacc[mt][t][2] = p2; sacc[mt][t][3] = p3;
                sm0 += p0 + p1; sm1 += p2 + p3;
            }
            sm0 += __shfl_xor_sync(0xffffffffu, sm0, 1);
            sm0 += __shfl_xor_sync(0xffffffffu, sm0, 2);
            sm1 += __shfl_xor_sync(0xffffffffu, sm1, 1);
            sm1 += __shfl_xor_sync(0xffffffffu, sm1, 2);
            lr[mt][0] = lr[mt][0] * al0 + sm0;
            lr[mt][1] = lr[mt][1] * al1 + sm1;
            #pragma unroll
            for (int t = 0; t < 8; t++) {
                oacc[mt][t][0] *= al0; oacc[mt][t][1] *= al0;
                oacc[mt][t][2] *= al1; oacc[mt][t][3] *= al1;
            }
        }

        // ---- O += P @ V (3-term; V frags shared across m-tiles) ----
        #pragma unroll
        for (int t = 0; t < 4; t++) {
            uint32_t ah[2][4], alr[2][4];
            #pragma unroll
            for (int mt = 0; mt < 2; mt++) {
                split2(sacc[mt][2*t][0],   sacc[mt][2*t][1],   ah[mt][0], alr[mt][0]);
                split2(sacc[mt][2*t][2],   sacc[mt][2*t][3],   ah[mt][1], alr[mt][1]);
                split2(sacc[mt][2*t+1][0], sacc[mt][2*t+1][1], ah[mt][2], alr[mt][2]);
                split2(sacc[mt][2*t+1][2], sacc[mt][2*t+1][3], ah[mt][3], alr[mt][3]);
            }
            #pragma unroll
            for (int u = 0; u < 4; u++) {
                int row = t * 16 + (lane & 7) + 8 * ((lane >> 3) & 1);
                int coln = u * 16 + 8 * (lane >> 4);
                uint32_t boff = (row * FPH + coln) * 2;
                uint32_t vh[4], vl[4];
                ldsm_x4t(aVh + boff, vh[0], vh[1], vh[2], vh[3]);
                ldsm_x4t(aVl + boff, vl[0], vl[1], vl[2], vl[3]);
                #pragma unroll
                for (int mt = 0; mt < 2; mt++) {
                    mma_bf16(oacc[mt][2*u],   ah[mt],  vh[0], vh[1]);
                    mma_bf16(oacc[mt][2*u],   ah[mt],  vl[0], vl[1]);
                    mma_bf16(oacc[mt][2*u],   alr[mt], vh[0], vh[1]);
                    mma_bf16(oacc[mt][2*u+1], ah[mt],  vh[2], vh[3]);
                    mma_bf16(oacc[mt][2*u+1], ah[mt],  vl[2], vl[3]);
                    mma_bf16(oacc[mt][2*u+1], alr[mt], vh[2], vh[3]);
                }
            }
        }
    }

    // ---- epilogue: O /= l, split to bf16 hi/lo ----
    #pragma unroll
    for (int mt = 0; mt < 2; mt++) {
        float i0 = 1.f / lr[mt][0], i1 = 1.f / lr[mt][1];
        #pragma unroll
        for (int t = 0; t < 8; t++) {
            int col = colbase + t * 8 + 2 * (lane & 3);
            size_t o0 = (rowbase + wrow0 + mt * 16 + (lane >> 2)) * EMB + col;
            size_t o1 = o0 + 8 * EMB;
            uint32_t h, l;
            split2(oacc[mt][t][0] * i0, oacc[mt][t][1] * i0, h, l);
            *(uint32_t*)(Oh + o0) = h;
            *(uint32_t*)(Ol + o0) = l;
            split2(oacc[mt][t][2] * i1, oacc[mt][t][3] * i1, h, l);
            *(uint32_t*)(Oh + o1) = h;
            *(uint32_t*)(Ol + o1) = l;
        }
    }
}

// ---------------------------------------------------------------------------
extern "C" void kernel_launch(void* const* d_in, const int* in_sizes, int n_in,
                              void* d_out, int out_size)
{
    const float* x  = (const float*)d_in[0];
    const int*   am = (const int*)d_in[1];
    const float* w[4] = { (const float*)d_in[2], (const float*)d_in[3],
                          (const float*)d_in[4], (const float*)d_in[5] };
    float* out = (float*)d_out;

    __nv_bfloat16 *xh, *xl, *wh, *wl, *Qh, *Ql, *Kh, *Kl, *Vh, *Vl, *Oh, *Ol;
    cudaGetSymbolAddress((void**)&xh, g_xh);
    cudaGetSymbolAddress((void**)&xl, g_xl);
    cudaGetSymbolAddress((void**)&wh, g_wh);
    cudaGetSymbolAddress((void**)&wl, g_wl);
    cudaGetSymbolAddress((void**)&Qh, g_Qh);
    cudaGetSymbolAddress((void**)&Ql, g_Ql);
    cudaGetSymbolAddress((void**)&Kh, g_Kh);
    cudaGetSymbolAddress((void**)&Kl, g_Kl);
    cudaGetSymbolAddress((void**)&Vh, g_Vh);
    cudaGetSymbolAddress((void**)&Vl, g_Vl);
    cudaGetSymbolAddress((void**)&Oh, g_Oh);
    cudaGetSymbolAddress((void**)&Ol, g_Ol);

    cudaFuncSetAttribute(gemm_tc, cudaFuncAttributeMaxDynamicSharedMemorySize, GEMM_SMEM);
    cudaFuncSetAttribute(flash_tc, cudaFuncAttributeMaxDynamicSharedMemorySize, FLASH_SMEM);

    split_k<<<(NTOK * EMB / 4 + 255) / 256, 256>>>(x, xh, xl, NTOK * EMB / 4);
    for (int i = 0; i < 4; i++)
        split_k<<<(EMB * EMB / 4 + 255) / 256, 256>>>(
            w[i], wh + (size_t)i * EMB * EMB, wl + (size_t)i * EMB * EMB, EMB * EMB / 4);

    // fused Q/K/V projections (blockIdx.z selects weight + destination)
    gemm_tc<<<dim3(EMB / 256, NTOK / 128, 3), 256, GEMM_SMEM>>>(
        xh, xl, wh, wl, nullptr, Qh, Ql, Kh, Kl, Vh, Vl);

    flash_tc<<<dim3(S_LEN / 256, NH, BATCH), 256, FLASH_SMEM>>>(
        Qh, Ql, Kh, Kl, Vh, Vl, am, Oh, Ol);

    // output projection -> fp32
    gemm_tc<<<dim3(EMB / 256, NTOK / 128, 1), 256, GEMM_SMEM>>>(
        Oh, Ol, wh + 3 * (size_t)EMB * EMB, wl + 3 * (size_t)EMB * EMB,
        out, nullptr, nullptr, nullptr, nullptr, nullptr, nullptr);
}

// round 12
// speedup vs baseline: 1.6029x; 1.6029x over previous
#include <cuda_runtime.h>
#include <cuda_fp16.h>
#include <cstdint>
#include <math.h>

#define S_LEN 2048
#define BATCH 4
#define EMB   1024
#define NH    16
#define HD    64
#define NTOK  (BATCH * S_LEN)   // 8192

// ---------------- scratch (device globals; no allocs allowed) --------------
__device__ __half g_xh[NTOK * EMB];
__device__ __half g_xl[NTOK * EMB];
__device__ __half g_w[4][EMB * EMB];      // weights: single fp16
__device__ __half g_Qh[NTOK * EMB];
__device__ __half g_Ql[NTOK * EMB];
__device__ __half g_K1[NTOK * EMB];       // K: single fp16
__device__ __half g_Vh[NTOK * EMB];
__device__ __half g_Vl[NTOK * EMB];
__device__ __half g_Oh[NTOK * EMB];
__device__ __half g_Ol[NTOK * EMB];

// ---------------- helpers --------------------------------------------------
__device__ __forceinline__ uint32_t smem_u32(const void* p) {
    uint32_t a;
    asm("{ .reg .u64 t; cvta.to.shared.u64 t, %1; cvt.u32.u64 %0, t; }" : "=r"(a) : "l"(p));
    return a;
}
__device__ __forceinline__ void ldsm_x4(uint32_t a, uint32_t& r0, uint32_t& r1,
                                        uint32_t& r2, uint32_t& r3) {
    asm volatile("ldmatrix.sync.aligned.m8n8.x4.shared.b16 {%0,%1,%2,%3}, [%4];"
                 : "=r"(r0), "=r"(r1), "=r"(r2), "=r"(r3) : "r"(a));
}
__device__ __forceinline__ void ldsm_x4t(uint32_t a, uint32_t& r0, uint32_t& r1,
                                         uint32_t& r2, uint32_t& r3) {
    asm volatile("ldmatrix.sync.aligned.m8n8.x4.trans.shared.b16 {%0,%1,%2,%3}, [%4];"
                 : "=r"(r0), "=r"(r1), "=r"(r2), "=r"(r3) : "r"(a));
}
__device__ __forceinline__ void mma_f16(float* d, const uint32_t* a,
                                        uint32_t b0, uint32_t b1) {
    asm volatile(
        "mma.sync.aligned.m16n8k16.row.col.f32.f16.f16.f32 "
        "{%0,%1,%2,%3}, {%4,%5,%6,%7}, {%8,%9}, {%0,%1,%2,%3};"
        : "+f"(d[0]), "+f"(d[1]), "+f"(d[2]), "+f"(d[3])
        : "r"(a[0]), "r"(a[1]), "r"(a[2]), "r"(a[3]), "r"(b0), "r"(b1));
}
__device__ __forceinline__ uint32_t pack2h(float x, float y) {
    __half2 h = __floats2half2_rn(x, y);
    return *(uint32_t*)&h;
}
__device__ __forceinline__ void split2h(float x, float y, uint32_t& hi, uint32_t& lo) {
    __half2 h = __floats2half2_rn(x, y);
    hi = *(uint32_t*)&h;
    lo = pack2h(x - __half2float(h.x), y - __half2float(h.y));
}
#define CP_ASYNC16(s, g) \
    asm volatile("cp.async.cg.shared.global [%0], [%1], 16;" :: "r"(s), "l"(g) : "memory")
#define CP_COMMIT() asm volatile("cp.async.commit_group;" ::: "memory")
#define CP_WAIT0()  asm volatile("cp.async.wait_group 0;" ::: "memory")

// ---------------------------------------------------------------------------
// input split: fp32 -> (hi, lo) fp16;  weight cvt: fp32 -> fp16
// ---------------------------------------------------------------------------
__global__ __launch_bounds__(256) void split_k(
    const float* __restrict__ src, __half* __restrict__ hi,
    __half* __restrict__ lo, int n4)
{
    int i = blockIdx.x * 256 + threadIdx.x;
    if (i >= n4) return;
    float4 v = ((const float4*)src)[i];
    float x[4] = {v.x, v.y, v.z, v.w};
    __half h[4], l[4];
    #pragma unroll
    for (int j = 0; j < 4; j++) {
        h[j] = __float2half_rn(x[j]);
        l[j] = __float2half_rn(x[j] - __half2float(h[j]));
    }
    ((uint2*)hi)[i] = *(uint2*)h;
    ((uint2*)lo)[i] = *(uint2*)l;
}

__global__ __launch_bounds__(256) void cvt_k(
    const float* __restrict__ src, __half* __restrict__ dst, int n4)
{
    int i = blockIdx.x * 256 + threadIdx.x;
    if (i >= n4) return;
    float4 v = ((const float4*)src)[i];
    __half h[4] = { __float2half_rn(v.x), __float2half_rn(v.y),
                    __float2half_rn(v.z), __float2half_rn(v.w) };
    ((uint2*)dst)[i] = *(uint2*)h;
}

// ---------------------------------------------------------------------------
// mma.sync 2-term fp16 GEMM: C = (Ah+Al) @ W_z^T.  CTA 128x128, warp 64x32,
// K chunk 64, 2-stage cp.async, one barrier per chunk.
// Epilogue per z: 0 -> split(Qh,Ql); 1 -> single(K1); 2 -> split(Vh,Vl);
// Cf != null -> fp32 out.
// ---------------------------------------------------------------------------
#define GP 72
#define GTILE_H (128 * GP)            // 9216 halves
#define GSTAGE_H (3 * GTILE_H)        // Ah, Al, B
#define GEMM_SMEM (2 * GSTAGE_H * 2)  // 110592 bytes

__global__ __launch_bounds__(256) void gemm_tc(
    const __half* __restrict__ Ah, const __half* __restrict__ Al,
    const __half* __restrict__ Wbase,
    float* __restrict__ Cf,
    __half* __restrict__ Qh, __half* __restrict__ Ql,
    __half* __restrict__ K1,
    __half* __restrict__ Vh, __half* __restrict__ Vl)
{
    extern __shared__ __half sm[];
    const uint32_t sb = smem_u32(sm);
    const int tid = threadIdx.x, lane = tid & 31, w = tid >> 5;
    const int wm = w & 1, wn = w >> 1;
    const int m0 = blockIdx.y * 128, n0 = blockIdx.x * 128;
    const int z = blockIdx.z;
    const __half* B = Wbase + (size_t)z * EMB * EMB;

    const __half* srcs[3] = {Ah, Al, B};
    const int r0s[3] = {m0, m0, n0};

    auto issue = [&](int k0, int st) {
        #pragma unroll
        for (int i = 0; i < 12; i++) {
            int idx = i * 256 + tid;              // 0..3071
            int t = idx >> 10, rel = idx & 1023;
            int row = rel >> 3, c8 = (rel & 7) * 8;
            const __half* g = srcs[t] + (size_t)(r0s[t] + row) * EMB + k0 + c8;
            uint32_t s = sb + (uint32_t)(st * GSTAGE_H + t * GTILE_H + row * GP + c8) * 2;
            CP_ASYNC16(s, g);
        }
        CP_COMMIT();
    };

    issue(0, 0);
    float acc[4][4][4] = {};

    for (int c = 0; c < 16; c++) {
        const int st = c & 1;
        CP_WAIT0();
        __syncthreads();
        if (c + 1 < 16) issue((c + 1) * 64, st ^ 1);

        const uint32_t abase = sb + (uint32_t)(st * GSTAGE_H) * 2;
        const uint32_t bbase = sb + (uint32_t)(st * GSTAGE_H + 2 * GTILE_H) * 2;
        #pragma unroll
        for (int kc = 0; kc < 4; kc++) {
            uint32_t af[4][4], alf[4][4], bf[2][4];
            #pragma unroll
            for (int mt = 0; mt < 4; mt++) {
                int row = wm * 64 + mt * 16 + (lane & 15);
                uint32_t a = abase + (row * GP + kc * 16 + 8 * (lane >> 4)) * 2;
                ldsm_x4(a, af[mt][0], af[mt][1], af[mt][2], af[mt][3]);
                ldsm_x4(a + GTILE_H * 2, alf[mt][0], alf[mt][1], alf[mt][2], alf[mt][3]);
            }
            #pragma unroll
            for (int u = 0; u < 2; u++) {
                int row = wn * 32 + u * 16 + (lane & 7) + 8 * ((lane >> 3) & 1);
                uint32_t b = bbase + (row * GP + kc * 16 + 8 * (lane >> 4)) * 2;
                ldsm_x4(b, bf[u][0], bf[u][1], bf[u][2], bf[u][3]);
            }
            #pragma unroll
            for (int mt = 0; mt < 4; mt++)
                #pragma unroll
                for (int u = 0; u < 2; u++) {
                    mma_f16(acc[mt][2*u],   af[mt],  bf[u][0], bf[u][2]);
                    mma_f16(acc[mt][2*u],   alf[mt], bf[u][0], bf[u][2]);
                    mma_f16(acc[mt][2*u+1], af[mt],  bf[u][1], bf[u][3]);
                    mma_f16(acc[mt][2*u+1], alf[mt], bf[u][1], bf[u][3]);
                }
        }
        __syncthreads();
    }

    #pragma unroll
    for (int mt = 0; mt < 4; mt++) {
        int grow = m0 + wm * 64 + mt * 16 + (lane >> 2);
        #pragma unroll
        for (int nt = 0; nt < 4; nt++) {
            int gcol = n0 + wn * 32 + nt * 8 + 2 * (lane & 3);
            float* a = acc[mt][nt];
            size_t o0 = (size_t)grow * EMB + gcol;
            size_t o1 = (size_t)(grow + 8) * EMB + gcol;
            if (Cf) {
                *(float2*)(Cf + o0) = make_float2(a[0], a[1]);
                *(float2*)(Cf + o1) = make_float2(a[2], a[3]);
            } else if (z == 1) {
                *(uint32_t*)(K1 + o0) = pack2h(a[0], a[1]);
                *(uint32_t*)(K1 + o1) = pack2h(a[2], a[3]);
            } else {
                __half* Ch = (z == 0) ? Qh : Vh;
                __half* Cl = (z == 0) ? Ql : Vl;
                uint32_t h, l;
                split2h(a[0], a[1], h, l);
                *(uint32_t*)(Ch + o0) = h;
                *(uint32_t*)(Cl + o0) = l;
                split2h(a[2], a[3], h, l);
                *(uint32_t*)(Ch + o1) = h;
                *(uint32_t*)(Cl + o1) = l;
            }
        }
    }
}

// ---------------------------------------------------------------------------
// Flash attention, mma.sync 2-term fp16.  S = (Qh+Ql)@K1^T, O += P@(Vh+Vl).
// CTA = 128 q-rows, 8 warps x 16 rows, 64-key tiles, cp.async 2-stage,
// qt-descending remap, per-warp masked-tile skip.
// ---------------------------------------------------------------------------
#define FPH 72
#define FQ_H (128 * FPH)              // 9216 halves
#define FK_H (64 * FPH)               // 4608 halves
#define FSTG_H (3 * FK_H)             // K, Vh, Vl per stage
#define FLASH_SMEM ((2 * FQ_H + 2 * FSTG_H) * 2 + 2 * 64 * 4)   // 92672 B

__global__ __launch_bounds__(256) void flash_tc(
    const __half* __restrict__ Qh, const __half* __restrict__ Ql,
    const __half* __restrict__ K1,
    const __half* __restrict__ Vh, const __half* __restrict__ Vl,
    const int* __restrict__ am,
    __half* __restrict__ Oh, __half* __restrict__ Ol)
{
    extern __shared__ __half sm[];
    const uint32_t sb = smem_u32(sm);
    int* ambuf = (int*)(sm + 2 * FQ_H + 2 * FSTG_H);

    const int tid = threadIdx.x, lane = tid & 31, w = tid >> 5;
    const int qt = (int)(gridDim.x - 1 - blockIdx.x);   // heavy tiles first
    const int q0 = qt * 128;
    const size_t rowbase = (size_t)blockIdx.z * S_LEN;
    const int colbase = blockIdx.y * HD;

    const __half* srcs[3] = {K1, Vh, Vl};

    auto prefetch = [&](int kt, int st) {
        const int k0 = kt * 64;
        #pragma unroll
        for (int i = 0; i < 6; i++) {
            int idx = i * 256 + tid;              // 0..1535
            int t = idx >> 9, j = idx & 511;
            int row = j >> 3, c8 = (j & 7) * 8;
            const __half* g = srcs[t] + (rowbase + k0 + row) * EMB + colbase + c8;
            uint32_t s = sb + (uint32_t)(2 * FQ_H + st * FSTG_H + t * FK_H + row * FPH + c8) * 2;
            CP_ASYNC16(s, g);
        }
        if (tid < 16) {
            const int* g = am + rowbase + k0 + tid * 4;
            uint32_t s = sb + (uint32_t)(2 * FQ_H + 2 * FSTG_H) * 2 + (st * 64 + tid * 4) * 4;
            CP_ASYNC16(s, g);
        }
        CP_COMMIT();
    };

    // Q tile (hi + lo)
    #pragma unroll
    for (int i = 0; i < 4; i++) {
        int idx = i * 256 + tid;
        int row = idx >> 3, c8 = (idx & 7) * 8;
        size_t go = (rowbase + q0 + row) * EMB + colbase + c8;
        *(float4*)&sm[row * FPH + c8]        = *(const float4*)&Qh[go];
        *(float4*)&sm[FQ_H + row * FPH + c8] = *(const float4*)&Ql[go];
    }
    prefetch(0, 0);

    float oacc[8][4] = {};
    float mr0 = -1e30f, mr1 = -1e30f, lr0 = 0.f, lr1 = 0.f;

    const uint32_t aQh = sb, aQl = sb + FQ_H * 2;
    const int qrow  = q0 + w * 16 + (lane >> 2);
    const int qmaxw = q0 + w * 16 + 15;
    const int nkt = 2 * qt + 2;

    for (int kt = 0; kt < nkt; kt++) {
        const int k0 = kt * 64;
        const int st = kt & 1;
        CP_WAIT0();
        __syncthreads();
        if (kt + 1 < nkt) prefetch(kt + 1, st ^ 1);

        if (k0 > qmaxw) continue;   // fully masked for this warp

        const uint32_t aK  = sb + (uint32_t)(2 * FQ_H + st * FSTG_H) * 2;
        const uint32_t aVh = aK + FK_H * 2;
        const uint32_t aVl = aVh + FK_H * 2;
        const int* amb = ambuf + st * 64;

        // ---- S = Q @ K^T (2-term: Qh, Ql vs single K) ----
        float sacc[8][4] = {};
        #pragma unroll
        for (int kc = 0; kc < 4; kc++) {
            uint32_t qa[4], qla[4];
            {
                int row = w * 16 + (lane & 15);
                uint32_t a = (row * FPH + kc * 16 + 8 * (lane >> 4)) * 2;
                ldsm_x4(aQh + a, qa[0], qa[1], qa[2], qa[3]);
                ldsm_x4(aQl + a, qla[0], qla[1], qla[2], qla[3]);
            }
            #pragma unroll
            for (int np = 0; np < 4; np++) {
                int row = np * 16 + (lane & 7) + 8 * ((lane >> 3) & 1);
                uint32_t boff = (row * FPH + kc * 16 + 8 * (lane >> 4)) * 2;
                uint32_t kh[4];
                ldsm_x4(aK + boff, kh[0], kh[1], kh[2], kh[3]);
                mma_f16(sacc[2*np],   qa,  kh[0], kh[2]);
                mma_f16(sacc[2*np],   qla, kh[0], kh[2]);
                mma_f16(sacc[2*np+1], qa,  kh[1], kh[3]);
                mma_f16(sacc[2*np+1], qla, kh[1], kh[3]);
            }
        }

        // ---- online softmax in fragments ----
        const bool needmask = (k0 + 63) > (q0 + w * 16);
        float mx0 = -1e30f, mx1 = -1e30f;
        #pragma unroll
        for (int t = 0; t < 8; t++) {
            int lc = t * 8 + 2 * (lane & 3);
            int a0 = amb[lc], a1 = amb[lc + 1];
            float s0 = a0 ? sacc[t][0] * 0.125f : -1e30f;
            float s1 = a1 ? sacc[t][1] * 0.125f : -1e30f;
            float s2 = a0 ? sacc[t][2] * 0.125f : -1e30f;
            float s3 = a1 ? sacc[t][3] * 0.125f : -1e30f;
            if (needmask) {
                int cg = k0 + lc;
                if (cg > qrow)         s0 = -1e30f;
                if (cg + 1 > qrow)     s1 = -1e30f;
                if (cg > qrow + 8)     s2 = -1e30f;
                if (cg + 1 > qrow + 8) s3 = -1e30f;
            }
            sacc[t][0] = s0; sacc[t][1] = s1; sacc[t][2] = s2; sacc[t][3] = s3;
            mx0 = fmaxf(mx0, fmaxf(s0, s1));
            mx1 = fmaxf(mx1, fmaxf(s2, s3));
        }
        mx0 = fmaxf(mx0, __shfl_xor_sync(0xffffffffu, mx0, 1));
        mx0 = fmaxf(mx0, __shfl_xor_sync(0xffffffffu, mx0, 2));
        mx1 = fmaxf(mx1, __shfl_xor_sync(0xffffffffu, mx1, 1));
        mx1 = fmaxf(mx1, __shfl_xor_sync(0xffffffffu, mx1, 2));
        float mn0 = fmaxf(mr0, mx0), mn1 = fmaxf(mr1, mx1);
        float al0 = __expf(mr0 - mn0), al1 = __expf(mr1 - mn1);
        mr0 = mn0; mr1 = mn1;
        float sm0 = 0.f, sm1 = 0.f;
        #pragma unroll
        for (int t = 0; t < 8; t++) {
            float p0 = __expf(sacc[t][0] - mn0);
            float p1 = __expf(sacc[t][1] - mn0);
            float p2 = __expf(sacc[t][2] - mn1);
            float p3 = __expf(sacc[t][3] - mn1);
            sacc[t][0] = p0; sacc[t][1] = p1; sacc[t][2] = p2; sacc[t][3] = p3;
            sm0 += p0 + p1; sm1 += p2 + p3;
        }
        sm0 += __shfl_xor_sync(0xffffffffu, sm0, 1);
        sm0 += __shfl_xor_sync(0xffffffffu, sm0, 2);
        sm1 += __shfl_xor_sync(0xffffffffu, sm1, 1);
        sm1 += __shfl_xor_sync(0xffffffffu, sm1, 2);
        lr0 = lr0 * al0 + sm0;
        lr1 = lr1 * al1 + sm1;
        #pragma unroll
        for (int t = 0; t < 8; t++) {
            oacc[t][0] *= al0; oacc[t][1] *= al0;
            oacc[t][2] *= al1; oacc[t][3] *= al1;
        }

        // ---- O += P @ V (P single fp16; V = Vh + Vl) ----
        #pragma unroll
        for (int t = 0; t < 4; t++) {
            uint32_t ph[4];
            ph[0] = pack2h(sacc[2*t][0],   sacc[2*t][1]);
            ph[1] = pack2h(sacc[2*t][2],   sacc[2*t][3]);
            ph[2] = pack2h(sacc[2*t+1][0], sacc[2*t+1][1]);
            ph[3] = pack2h(sacc[2*t+1][2], sacc[2*t+1][3]);
            #pragma unroll
            for (int u = 0; u < 4; u++) {
                int row = t * 16 + (lane & 7) + 8 * ((lane >> 3) & 1);
                int coln = u * 16 + 8 * (lane >> 4);
                uint32_t boff = (row * FPH + coln) * 2;
                uint32_t vh[4], vl[4];
                ldsm_x4t(aVh + boff, vh[0], vh[1], vh[2], vh[3]);
                ldsm_x4t(aVl + boff, vl[0], vl[1], vl[2], vl[3]);
                mma_f16(oacc[2*u],   ph, vh[0], vh[1]);
                mma_f16(oacc[2*u],   ph, vl[0], vl[1]);
                mma_f16(oacc[2*u+1], ph, vh[2], vh[3]);
                mma_f16(oacc[2*u+1], ph, vl[2], vl[3]);
            }
        }
    }

    // ---- epilogue: O /= l, split to fp16 hi/lo ----
    float i0 = 1.f / lr0, i1 = 1.f / lr1;
    #pragma unroll
    for (int t = 0; t < 8; t++) {
        int col = colbase + t * 8 + 2 * (lane & 3);
        size_t o0 = (rowbase + q0 + w * 16 + (lane >> 2)) * EMB + col;
        size_t o1 = o0 + 8 * EMB;
        uint32_t h, l;
        split2h(oacc[t][0] * i0, oacc[t][1] * i0, h, l);
        *(uint32_t*)(Oh + o0) = h;
        *(uint32_t*)(Ol + o0) = l;
        split2h(oacc[t][2] * i1, oacc[t][3] * i1, h, l);
        *(uint32_t*)(Oh + o1) = h;
        *(uint32_t*)(Ol + o1) = l;
    }
}

// ---------------------------------------------------------------------------
extern "C" void kernel_launch(void* const* d_in, const int* in_sizes, int n_in,
                              void* d_out, int out_size)
{
    const float* x  = (const float*)d_in[0];
    const int*   am = (const int*)d_in[1];
    const float* w[4] = { (const float*)d_in[2], (const float*)d_in[3],
                          (const float*)d_in[4], (const float*)d_in[5] };
    float* out = (float*)d_out;

    __half *xh, *xl, *wp, *Qh, *Ql, *K1, *Vh, *Vl, *Oh, *Ol;
    cudaGetSymbolAddress((void**)&xh, g_xh);
    cudaGetSymbolAddress((void**)&xl, g_xl);
    cudaGetSymbolAddress((void**)&wp, g_w);
    cudaGetSymbolAddress((void**)&Qh, g_Qh);
    cudaGetSymbolAddress((void**)&Ql, g_Ql);
    cudaGetSymbolAddress((void**)&K1, g_K1);
    cudaGetSymbolAddress((void**)&Vh, g_Vh);
    cudaGetSymbolAddress((void**)&Vl, g_Vl);
    cudaGetSymbolAddress((void**)&Oh, g_Oh);
    cudaGetSymbolAddress((void**)&Ol, g_Ol);

    cudaFuncSetAttribute(gemm_tc, cudaFuncAttributeMaxDynamicSharedMemorySize, GEMM_SMEM);
    cudaFuncSetAttribute(flash_tc, cudaFuncAttributeMaxDynamicSharedMemorySize, FLASH_SMEM);

    split_k<<<(NTOK * EMB / 4 + 255) / 256, 256>>>(x, xh, xl, NTOK * EMB / 4);
    for (int i = 0; i < 4; i++)
        cvt_k<<<(EMB * EMB / 4 + 255) / 256, 256>>>(
            w[i], wp + (size_t)i * EMB * EMB, EMB * EMB / 4);

    // fused Q/K/V projections (blockIdx.z selects weight + destination)
    gemm_tc<<<dim3(EMB / 128, NTOK / 128, 3), 256, GEMM_SMEM>>>(
        xh, xl, wp, nullptr, Qh, Ql, K1, Vh, Vl);

    flash_tc<<<dim3(S_LEN / 128, NH, BATCH), 256, FLASH_SMEM>>>(
        Qh, Ql, K1, Vh, Vl, am, Oh, Ol);

    // output projection -> fp32
    gemm_tc<<<dim3(EMB / 128, NTOK / 128, 1), 256, GEMM_SMEM>>>(
        Oh, Ol, wp + 3 * (size_t)EMB * EMB, out,
        nullptr, nullptr, nullptr, nullptr, nullptr);
}

// round 13
// speedup vs baseline: 1.8295x; 1.1414x over previous
#include <cuda_runtime.h>
#include <cuda_fp16.h>
#include <cstdint>
#include <math.h>

#define S_LEN 2048
#define BATCH 4
#define EMB   1024
#define NH    16
#define HD    64
#define NTOK  (BATCH * S_LEN)   // 8192

// ---------------- scratch (device globals; no allocs allowed) --------------
__device__ __half g_xh[NTOK * EMB];
__device__ __half g_xl[NTOK * EMB];
__device__ __half g_w[4][EMB * EMB];      // weights: single fp16
__device__ __half g_Qh[NTOK * EMB];
__device__ __half g_Ql[NTOK * EMB];
__device__ __half g_K1[NTOK * EMB];       // K: single fp16
__device__ __half g_V1[NTOK * EMB];       // V: single fp16
__device__ __half g_O1[NTOK * EMB];       // attn out: single fp16

// ---------------- helpers --------------------------------------------------
__device__ __forceinline__ uint32_t smem_u32(const void* p) {
    uint32_t a;
    asm("{ .reg .u64 t; cvta.to.shared.u64 t, %1; cvt.u32.u64 %0, t; }" : "=r"(a) : "l"(p));
    return a;
}
__device__ __forceinline__ void ldsm_x4(uint32_t a, uint32_t& r0, uint32_t& r1,
                                        uint32_t& r2, uint32_t& r3) {
    asm volatile("ldmatrix.sync.aligned.m8n8.x4.shared.b16 {%0,%1,%2,%3}, [%4];"
                 : "=r"(r0), "=r"(r1), "=r"(r2), "=r"(r3) : "r"(a));
}
__device__ __forceinline__ void ldsm_x4t(uint32_t a, uint32_t& r0, uint32_t& r1,
                                         uint32_t& r2, uint32_t& r3) {
    asm volatile("ldmatrix.sync.aligned.m8n8.x4.trans.shared.b16 {%0,%1,%2,%3}, [%4];"
                 : "=r"(r0), "=r"(r1), "=r"(r2), "=r"(r3) : "r"(a));
}
__device__ __forceinline__ void mma_f16(float* d, const uint32_t* a,
                                        uint32_t b0, uint32_t b1) {
    asm volatile(
        "mma.sync.aligned.m16n8k16.row.col.f32.f16.f16.f32 "
        "{%0,%1,%2,%3}, {%4,%5,%6,%7}, {%8,%9}, {%0,%1,%2,%3};"
        : "+f"(d[0]), "+f"(d[1]), "+f"(d[2]), "+f"(d[3])
        : "r"(a[0]), "r"(a[1]), "r"(a[2]), "r"(a[3]), "r"(b0), "r"(b1));
}
__device__ __forceinline__ uint32_t pack2h(float x, float y) {
    __half2 h = __floats2half2_rn(x, y);
    return *(uint32_t*)&h;
}
__device__ __forceinline__ void split2h(float x, float y, uint32_t& hi, uint32_t& lo) {
    __half2 h = __floats2half2_rn(x, y);
    hi = *(uint32_t*)&h;
    lo = pack2h(x - __half2float(h.x), y - __half2float(h.y));
}
#define CP_ASYNC16(s, g) \
    asm volatile("cp.async.cg.shared.global [%0], [%1], 16;" :: "r"(s), "l"(g) : "memory")
#define CP_COMMIT() asm volatile("cp.async.commit_group;" ::: "memory")
#define CP_WAIT0()  asm volatile("cp.async.wait_group 0;" ::: "memory")

// ---------------------------------------------------------------------------
// input split: fp32 -> (hi, lo) fp16;  weight cvt: fp32 -> fp16
// ---------------------------------------------------------------------------
__global__ __launch_bounds__(256) void split_k(
    const float* __restrict__ src, __half* __restrict__ hi,
    __half* __restrict__ lo, int n4)
{
    int i = blockIdx.x * 256 + threadIdx.x;
    if (i >= n4) return;
    float4 v = ((const float4*)src)[i];
    float x[4] = {v.x, v.y, v.z, v.w};
    __half h[4], l[4];
    #pragma unroll
    for (int j = 0; j < 4; j++) {
        h[j] = __float2half_rn(x[j]);
        l[j] = __float2half_rn(x[j] - __half2float(h[j]));
    }
    ((uint2*)hi)[i] = *(uint2*)h;
    ((uint2*)lo)[i] = *(uint2*)l;
}

__global__ __launch_bounds__(256) void cvt_k(
    const float* __restrict__ src, __half* __restrict__ dst, int n4)
{
    int i = blockIdx.x * 256 + threadIdx.x;
    if (i >= n4) return;
    float4 v = ((const float4*)src)[i];
    __half h[4] = { __float2half_rn(v.x), __float2half_rn(v.y),
                    __float2half_rn(v.z), __float2half_rn(v.w) };
    ((uint2*)dst)[i] = *(uint2*)h;
}

// ---------------------------------------------------------------------------
// mma.sync fp16 GEMM, ATERMS-term A: C = (Ah[+Al]) @ W_z^T.
// CTA 128x128, warp 64x32, K chunk 64, 2-stage cp.async, 1 barrier/chunk.
// Epilogue: Cf!=null -> fp32; else z: 0 -> split(Qh,Ql); 1 -> K1; 2 -> V1.
// ---------------------------------------------------------------------------
#define GP 72
#define GTILE_H (128 * GP)            // 9216 halves

template<int ATERMS>
__global__ __launch_bounds__(256) void gemm_tc(
    const __half* __restrict__ Ah, const __half* __restrict__ Al,
    const __half* __restrict__ Wbase,
    float* __restrict__ Cf,
    __half* __restrict__ Qh, __half* __restrict__ Ql,
    __half* __restrict__ K1, __half* __restrict__ V1)
{
    constexpr int NT = ATERMS + 1;            // tiles per stage
    constexpr int STG = NT * GTILE_H;
    extern __shared__ __half sm[];
    const uint32_t sb = smem_u32(sm);
    const int tid = threadIdx.x, lane = tid & 31, w = tid >> 5;
    const int wm = w & 1, wn = w >> 1;
    const int m0 = blockIdx.y * 128, n0 = blockIdx.x * 128;
    const int z = blockIdx.z;
    const __half* B = Wbase + (size_t)z * EMB * EMB;

    const __half* srcs[NT];
    int r0s[NT];
    srcs[0] = Ah; r0s[0] = m0;
    if (ATERMS == 2) { srcs[1] = Al; r0s[1] = m0; }
    srcs[NT - 1] = B; r0s[NT - 1] = n0;

    auto issue = [&](int k0, int st) {
        #pragma unroll
        for (int i = 0; i < NT * 4; i++) {
            int idx = i * 256 + tid;
            int t = idx >> 10, rel = idx & 1023;
            int row = rel >> 3, c8 = (rel & 7) * 8;
            const __half* g = srcs[t] + (size_t)(r0s[t] + row) * EMB + k0 + c8;
            uint32_t s = sb + (uint32_t)(st * STG + t * GTILE_H + row * GP + c8) * 2;
            CP_ASYNC16(s, g);
        }
        CP_COMMIT();
    };

    issue(0, 0);
    float acc[4][4][4] = {};

    for (int c = 0; c < 16; c++) {
        const int st = c & 1;
        CP_WAIT0();
        __syncthreads();
        if (c + 1 < 16) issue((c + 1) * 64, st ^ 1);

        const uint32_t abase = sb + (uint32_t)(st * STG) * 2;
        const uint32_t bbase = sb + (uint32_t)(st * STG + (NT - 1) * GTILE_H) * 2;
        #pragma unroll
        for (int kc = 0; kc < 4; kc++) {
            uint32_t af[4][4], alf[4][4], bf[2][4];
            #pragma unroll
            for (int mt = 0; mt < 4; mt++) {
                int row = wm * 64 + mt * 16 + (lane & 15);
                uint32_t a = abase + (row * GP + kc * 16 + 8 * (lane >> 4)) * 2;
                ldsm_x4(a, af[mt][0], af[mt][1], af[mt][2], af[mt][3]);
                if (ATERMS == 2)
                    ldsm_x4(a + GTILE_H * 2, alf[mt][0], alf[mt][1], alf[mt][2], alf[mt][3]);
            }
            #pragma unroll
            for (int u = 0; u < 2; u++) {
                int row = wn * 32 + u * 16 + (lane & 7) + 8 * ((lane >> 3) & 1);
                uint32_t b = bbase + (row * GP + kc * 16 + 8 * (lane >> 4)) * 2;
                ldsm_x4(b, bf[u][0], bf[u][1], bf[u][2], bf[u][3]);
            }
            #pragma unroll
            for (int mt = 0; mt < 4; mt++)
                #pragma unroll
                for (int u = 0; u < 2; u++) {
                    mma_f16(acc[mt][2*u],   af[mt],  bf[u][0], bf[u][2]);
                    mma_f16(acc[mt][2*u+1], af[mt],  bf[u][1], bf[u][3]);
                    if (ATERMS == 2) {
                        mma_f16(acc[mt][2*u],   alf[mt], bf[u][0], bf[u][2]);
                        mma_f16(acc[mt][2*u+1], alf[mt], bf[u][1], bf[u][3]);
                    }
                }
        }
        __syncthreads();
    }

    #pragma unroll
    for (int mt = 0; mt < 4; mt++) {
        int grow = m0 + wm * 64 + mt * 16 + (lane >> 2);
        #pragma unroll
        for (int nt = 0; nt < 4; nt++) {
            int gcol = n0 + wn * 32 + nt * 8 + 2 * (lane & 3);
            float* a = acc[mt][nt];
            size_t o0 = (size_t)grow * EMB + gcol;
            size_t o1 = (size_t)(grow + 8) * EMB + gcol;
            if (Cf) {
                *(float2*)(Cf + o0) = make_float2(a[0], a[1]);
                *(float2*)(Cf + o1) = make_float2(a[2], a[3]);
            } else if (z == 0) {
                uint32_t h, l;
                split2h(a[0], a[1], h, l);
                *(uint32_t*)(Qh + o0) = h;
                *(uint32_t*)(Ql + o0) = l;
                split2h(a[2], a[3], h, l);
                *(uint32_t*)(Qh + o1) = h;
                *(uint32_t*)(Ql + o1) = l;
            } else {
                __half* C1 = (z == 1) ? K1 : V1;
                *(uint32_t*)(C1 + o0) = pack2h(a[0], a[1]);
                *(uint32_t*)(C1 + o1) = pack2h(a[2], a[3]);
            }
        }
    }
}

#define GEMM_SMEM_2 (2 * 3 * GTILE_H * 2)   // 110592 B
#define GEMM_SMEM_1 (2 * 2 * GTILE_H * 2)   // 73728 B

// ---------------------------------------------------------------------------
// Flash attention: S = (Qh+Ql)@K1^T, O += P@V1 (single V).
// CTA = 128 q-rows, 8 warps x 16 rows, 64-key tiles, cp.async 2-stage,
// qt-descending remap, per-warp masked-tile skip.  O out: single fp16.
// ---------------------------------------------------------------------------
#define FPH 72
#define FQ_H (128 * FPH)              // 9216 halves
#define FK_H (64 * FPH)               // 4608 halves
#define FSTG_H (2 * FK_H)             // K, V per stage
#define FLASH_SMEM ((2 * FQ_H + 2 * FSTG_H) * 2 + 2 * 64 * 4)   // 74240 B

__global__ __launch_bounds__(256) void flash_tc(
    const __half* __restrict__ Qh, const __half* __restrict__ Ql,
    const __half* __restrict__ K1, const __half* __restrict__ V1,
    const int* __restrict__ am, __half* __restrict__ O1)
{
    extern __shared__ __half sm[];
    const uint32_t sb = smem_u32(sm);
    int* ambuf = (int*)(sm + 2 * FQ_H + 2 * FSTG_H);

    const int tid = threadIdx.x, lane = tid & 31, w = tid >> 5;
    const int qt = (int)(gridDim.x - 1 - blockIdx.x);   // heavy tiles first
    const int q0 = qt * 128;
    const size_t rowbase = (size_t)blockIdx.z * S_LEN;
    const int colbase = blockIdx.y * HD;

    const __half* srcs[2] = {K1, V1};

    auto prefetch = [&](int kt, int st) {
        const int k0 = kt * 64;
        #pragma unroll
        for (int i = 0; i < 4; i++) {
            int idx = i * 256 + tid;              // 0..1023
            int t = idx >> 9, j = idx & 511;
            int row = j >> 3, c8 = (j & 7) * 8;
            const __half* g = srcs[t] + (rowbase + k0 + row) * EMB + colbase + c8;
            uint32_t s = sb + (uint32_t)(2 * FQ_H + st * FSTG_H + t * FK_H + row * FPH + c8) * 2;
            CP_ASYNC16(s, g);
        }
        if (tid < 16) {
            const int* g = am + rowbase + k0 + tid * 4;
            uint32_t s = sb + (uint32_t)(2 * FQ_H + 2 * FSTG_H) * 2 + (st * 64 + tid * 4) * 4;
            CP_ASYNC16(s, g);
        }
        CP_COMMIT();
    };

    // Q tile (hi + lo)
    #pragma unroll
    for (int i = 0; i < 4; i++) {
        int idx = i * 256 + tid;
        int row = idx >> 3, c8 = (idx & 7) * 8;
        size_t go = (rowbase + q0 + row) * EMB + colbase + c8;
        *(float4*)&sm[row * FPH + c8]        = *(const float4*)&Qh[go];
        *(float4*)&sm[FQ_H + row * FPH + c8] = *(const float4*)&Ql[go];
    }
    prefetch(0, 0);

    float oacc[8][4] = {};
    float mr0 = -1e30f, mr1 = -1e30f, lr0 = 0.f, lr1 = 0.f;

    const uint32_t aQh = sb, aQl = sb + FQ_H * 2;
    const int qrow  = q0 + w * 16 + (lane >> 2);
    const int qmaxw = q0 + w * 16 + 15;
    const int nkt = 2 * qt + 2;

    for (int kt = 0; kt < nkt; kt++) {
        const int k0 = kt * 64;
        const int st = kt & 1;
        CP_WAIT0();
        __syncthreads();
        if (kt + 1 < nkt) prefetch(kt + 1, st ^ 1);

        if (k0 > qmaxw) continue;   // fully masked for this warp

        const uint32_t aK = sb + (uint32_t)(2 * FQ_H + st * FSTG_H) * 2;
        const uint32_t aV = aK + FK_H * 2;
        const int* amb = ambuf + st * 64;

        // ---- S = Q @ K^T (2-term Q split vs single K) ----
        float sacc[8][4] = {};
        #pragma unroll
        for (int kc = 0; kc < 4; kc++) {
            uint32_t qa[4], qla[4];
            {
                int row = w * 16 + (lane & 15);
                uint32_t a = (row * FPH + kc * 16 + 8 * (lane >> 4)) * 2;
                ldsm_x4(aQh + a, qa[0], qa[1], qa[2], qa[3]);
                ldsm_x4(aQl + a, qla[0], qla[1], qla[2], qla[3]);
            }
            #pragma unroll
            for (int np = 0; np < 4; np++) {
                int row = np * 16 + (lane & 7) + 8 * ((lane >> 3) & 1);
                uint32_t boff = (row * FPH + kc * 16 + 8 * (lane >> 4)) * 2;
                uint32_t kh[4];
                ldsm_x4(aK + boff, kh[0], kh[1], kh[2], kh[3]);
                mma_f16(sacc[2*np],   qa,  kh[0], kh[2]);
                mma_f16(sacc[2*np],   qla, kh[0], kh[2]);
                mma_f16(sacc[2*np+1], qa,  kh[1], kh[3]);
                mma_f16(sacc[2*np+1], qla, kh[1], kh[3]);
            }
        }

        // ---- online softmax in fragments ----
        const bool needmask = (k0 + 63) > (q0 + w * 16);
        float mx0 = -1e30f, mx1 = -1e30f;
        #pragma unroll
        for (int t = 0; t < 8; t++) {
            int lc = t * 8 + 2 * (lane & 3);
            int a0 = amb[lc], a1 = amb[lc + 1];
            float s0 = a0 ? sacc[t][0] * 0.125f : -1e30f;
            float s1 = a1 ? sacc[t][1] * 0.125f : -1e30f;
            float s2 = a0 ? sacc[t][2] * 0.125f : -1e30f;
            float s3 = a1 ? sacc[t][3] * 0.125f : -1e30f;
            if (needmask) {
                int cg = k0 + lc;
                if (cg > qrow)         s0 = -1e30f;
                if (cg + 1 > qrow)     s1 = -1e30f;
                if (cg > qrow + 8)     s2 = -1e30f;
                if (cg + 1 > qrow + 8) s3 = -1e30f;
            }
            sacc[t][0] = s0; sacc[t][1] = s1; sacc[t][2] = s2; sacc[t][3] = s3;
            mx0 = fmaxf(mx0, fmaxf(s0, s1));
            mx1 = fmaxf(mx1, fmaxf(s2, s3));
        }
        mx0 = fmaxf(mx0, __shfl_xor_sync(0xffffffffu, mx0, 1));
        mx0 = fmaxf(mx0, __shfl_xor_sync(0xffffffffu, mx0, 2));
        mx1 = fmaxf(mx1, __shfl_xor_sync(0xffffffffu, mx1, 1));
        mx1 = fmaxf(mx1, __shfl_xor_sync(0xffffffffu, mx1, 2));
        float mn0 = fmaxf(mr0, mx0), mn1 = fmaxf(mr1, mx1);
        float al0 = __expf(mr0 - mn0), al1 = __expf(mr1 - mn1);
        mr0 = mn0; mr1 = mn1;
        float sm0 = 0.f, sm1 = 0.f;
        #pragma unroll
        for (int t = 0; t < 8; t++) {
            float p0 = __expf(sacc[t][0] - mn0);
            float p1 = __expf(sacc[t][1] - mn0);
            float p2 = __expf(sacc[t][2] - mn1);
            float p3 = __expf(sacc[t][3] - mn1);
            sacc[t][0] = p0; sacc[t][1] = p1; sacc[t][2] = p2; sacc[t][3] = p3;
            sm0 += p0 + p1; sm1 += p2 + p3;
        }
        sm0 += __shfl_xor_sync(0xffffffffu, sm0, 1);
        sm0 += __shfl_xor_sync(0xffffffffu, sm0, 2);
        sm1 += __shfl_xor_sync(0xffffffffu, sm1, 1);
        sm1 += __shfl_xor_sync(0xffffffffu, sm1, 2);
        lr0 = lr0 * al0 + sm0;
        lr1 = lr1 * al1 + sm1;
        #pragma unroll
        for (int t = 0; t < 8; t++) {
            oacc[t][0] *= al0; oacc[t][1] *= al0;
            oacc[t][2] *= al1; oacc[t][3] *= al1;
        }

        // ---- O += P @ V (P single fp16, V single fp16) ----
        #pragma unroll
        for (int t = 0; t < 4; t++) {
            uint32_t ph[4];
            ph[0] = pack2h(sacc[2*t][0],   sacc[2*t][1]);
            ph[1] = pack2h(sacc[2*t][2],   sacc[2*t][3]);
            ph[2] = pack2h(sacc[2*t+1][0], sacc[2*t+1][1]);
            ph[3] = pack2h(sacc[2*t+1][2], sacc[2*t+1][3]);
            #pragma unroll
            for (int u = 0; u < 4; u++) {
                int row = t * 16 + (lane & 7) + 8 * ((lane >> 3) & 1);
                int coln = u * 16 + 8 * (lane >> 4);
                uint32_t boff = (row * FPH + coln) * 2;
                uint32_t vh[4];
                ldsm_x4t(aV + boff, vh[0], vh[1], vh[2], vh[3]);
                mma_f16(oacc[2*u],   ph, vh[0], vh[1]);
                mma_f16(oacc[2*u+1], ph, vh[2], vh[3]);
            }
        }
    }

    // ---- epilogue: O /= l, single fp16 ----
    float i0 = 1.f / lr0, i1 = 1.f / lr1;
    #pragma unroll
    for (int t = 0; t < 8; t++) {
        int col = colbase + t * 8 + 2 * (lane & 3);
        size_t o0 = (rowbase + q0 + w * 16 + (lane >> 2)) * EMB + col;
        size_t o1 = o0 + 8 * EMB;
        *(uint32_t*)(O1 + o0) = pack2h(oacc[t][0] * i0, oacc[t][1] * i0);
        *(uint32_t*)(O1 + o1) = pack2h(oacc[t][2] * i1, oacc[t][3] * i1);
    }
}

// ---------------------------------------------------------------------------
extern "C" void kernel_launch(void* const* d_in, const int* in_sizes, int n_in,
                              void* d_out, int out_size)
{
    const float* x  = (const float*)d_in[0];
    const int*   am = (const int*)d_in[1];
    const float* w[4] = { (const float*)d_in[2], (const float*)d_in[3],
                          (const float*)d_in[4], (const float*)d_in[5] };
    float* out = (float*)d_out;

    __half *xh, *xl, *wp, *Qh, *Ql, *K1, *V1, *O1;
    cudaGetSymbolAddress((void**)&xh, g_xh);
    cudaGetSymbolAddress((void**)&xl, g_xl);
    cudaGetSymbolAddress((void**)&wp, g_w);
    cudaGetSymbolAddress((void**)&Qh, g_Qh);
    cudaGetSymbolAddress((void**)&Ql, g_Ql);
    cudaGetSymbolAddress((void**)&K1, g_K1);
    cudaGetSymbolAddress((void**)&V1, g_V1);
    cudaGetSymbolAddress((void**)&O1, g_O1);

    cudaFuncSetAttribute(gemm_tc<2>, cudaFuncAttributeMaxDynamicSharedMemorySize, GEMM_SMEM_2);
    cudaFuncSetAttribute(gemm_tc<1>, cudaFuncAttributeMaxDynamicSharedMemorySize, GEMM_SMEM_1);
    cudaFuncSetAttribute(flash_tc, cudaFuncAttributeMaxDynamicSharedMemorySize, FLASH_SMEM);

    split_k<<<(NTOK * EMB / 4 + 255) / 256, 256>>>(x, xh, xl, NTOK * EMB / 4);
    for (int i = 0; i < 4; i++)
        cvt_k<<<(EMB * EMB / 4 + 255) / 256, 256>>>(
            w[i], wp + (size_t)i * EMB * EMB, EMB * EMB / 4);

    // fused Q/K/V projections: 2-term A (xh + xl)
    gemm_tc<2><<<dim3(EMB / 128, NTOK / 128, 3), 256, GEMM_SMEM_2>>>(
        xh, xl, wp, nullptr, Qh, Ql, K1, V1);

    flash_tc<<<dim3(S_LEN / 128, NH, BATCH), 256, FLASH_SMEM>>>(
        Qh, Ql, K1, V1, am, O1);

    // output projection: 1-term A (single O) -> fp32
    gemm_tc<1><<<dim3(EMB / 128, NTOK / 128, 1), 256, GEMM_SMEM_1>>>(
        O1, nullptr, wp + 3 * (size_t)EMB * EMB, out,
        nullptr, nullptr, nullptr, nullptr);
}

// round 14
// speedup vs baseline: 2.6267x; 1.4358x over previous
#include <cuda_runtime.h>
#include <cuda_fp16.h>
#include <cstdint>
#include <math.h>

#define S_LEN 2048
#define BATCH 4
#define EMB   1024
#define NH    16
#define HD    64
#define NTOK  (BATCH * S_LEN)   // 8192

// ---------------- scratch (device globals; no allocs allowed) --------------
__device__ __half g_x1[NTOK * EMB];
__device__ __half g_w[4][EMB * EMB];
__device__ __half g_Q1[NTOK * EMB];
__device__ __half g_K1[NTOK * EMB];
__device__ __half g_V1[NTOK * EMB];
__device__ __half g_O1[NTOK * EMB];

// ---------------- helpers --------------------------------------------------
__device__ __forceinline__ uint32_t smem_u32(const void* p) {
    uint32_t a;
    asm("{ .reg .u64 t; cvta.to.shared.u64 t, %1; cvt.u32.u64 %0, t; }" : "=r"(a) : "l"(p));
    return a;
}
__device__ __forceinline__ void ldsm_x4(uint32_t a, uint32_t& r0, uint32_t& r1,
                                        uint32_t& r2, uint32_t& r3) {
    asm volatile("ldmatrix.sync.aligned.m8n8.x4.shared.b16 {%0,%1,%2,%3}, [%4];"
                 : "=r"(r0), "=r"(r1), "=r"(r2), "=r"(r3) : "r"(a));
}
__device__ __forceinline__ void ldsm_x4t(uint32_t a, uint32_t& r0, uint32_t& r1,
                                         uint32_t& r2, uint32_t& r3) {
    asm volatile("ldmatrix.sync.aligned.m8n8.x4.trans.shared.b16 {%0,%1,%2,%3}, [%4];"
                 : "=r"(r0), "=r"(r1), "=r"(r2), "=r"(r3) : "r"(a));
}
__device__ __forceinline__ void mma_f16(float* d, const uint32_t* a,
                                        uint32_t b0, uint32_t b1) {
    asm volatile(
        "mma.sync.aligned.m16n8k16.row.col.f32.f16.f16.f32 "
        "{%0,%1,%2,%3}, {%4,%5,%6,%7}, {%8,%9}, {%0,%1,%2,%3};"
        : "+f"(d[0]), "+f"(d[1]), "+f"(d[2]), "+f"(d[3])
        : "r"(a[0]), "r"(a[1]), "r"(a[2]), "r"(a[3]), "r"(b0), "r"(b1));
}
__device__ __forceinline__ uint32_t pack2h(float x, float y) {
    __half2 h = __floats2half2_rn(x, y);
    return *(uint32_t*)&h;
}
#define CP_ASYNC16(s, g) \
    asm volatile("cp.async.cg.shared.global [%0], [%1], 16;" :: "r"(s), "l"(g) : "memory")
#define CP_COMMIT() asm volatile("cp.async.commit_group;" ::: "memory")
#define CP_WAIT0()  asm volatile("cp.async.wait_group 0;" ::: "memory")

// ---------------------------------------------------------------------------
// fp32 -> fp16 convert (vectorized)
// ---------------------------------------------------------------------------
__global__ __launch_bounds__(256) void cvt_k(
    const float* __restrict__ src, __half* __restrict__ dst, int n4)
{
    int i = blockIdx.x * 256 + threadIdx.x;
    if (i >= n4) return;
    float4 v = ((const float4*)src)[i];
    __half h[4] = { __float2half_rn(v.x), __float2half_rn(v.y),
                    __float2half_rn(v.z), __float2half_rn(v.w) };
    ((uint2*)dst)[i] = *(uint2*)h;
}

// 4 weight matrices in one launch (w dst is contiguous g_w block)
__global__ __launch_bounds__(256) void cvt_w4(
    const float* __restrict__ w0, const float* __restrict__ w1,
    const float* __restrict__ w2, const float* __restrict__ w3,
    __half* __restrict__ dst)
{
    const int per = EMB * EMB / 4;       // float4 chunks per matrix
    int i = blockIdx.x * 256 + threadIdx.x;
    int z = i / per, j = i % per;
    if (z >= 4) return;
    const float* src = (z == 0) ? w0 : (z == 1) ? w1 : (z == 2) ? w2 : w3;
    float4 v = ((const float4*)src)[j];
    __half h[4] = { __float2half_rn(v.x), __float2half_rn(v.y),
                    __float2half_rn(v.z), __float2half_rn(v.w) };
    ((uint2*)dst)[i] = *(uint2*)h;
}

// ---------------------------------------------------------------------------
// mma.sync fp16 GEMM (single-term): C = A1 @ W_z^T.
// CTA 128x128, warp 64x32, K chunk 64, 2-stage cp.async, 1 barrier/chunk.
// Epilogue: Cf!=null -> fp32; else z: 0 -> Q1; 1 -> K1; 2 -> V1 (fp16).
// ---------------------------------------------------------------------------
#define GP 72
#define GTILE_H (128 * GP)              // 9216 halves
#define GSTG_H  (2 * GTILE_H)           // A, B per stage
#define GEMM_SMEM (2 * GSTG_H * 2)      // 73728 B

__global__ __launch_bounds__(256) void gemm_tc(
    const __half* __restrict__ A1, const __half* __restrict__ Wbase,
    float* __restrict__ Cf,
    __half* __restrict__ Q1, __half* __restrict__ K1, __half* __restrict__ V1)
{
    extern __shared__ __half sm[];
    const uint32_t sb = smem_u32(sm);
    const int tid = threadIdx.x, lane = tid & 31, w = tid >> 5;
    const int wm = w & 1, wn = w >> 1;
    const int m0 = blockIdx.y * 128, n0 = blockIdx.x * 128;
    const int z = blockIdx.z;
    const __half* B = Wbase + (size_t)z * EMB * EMB;

    const __half* srcs[2] = {A1, B};
    const int r0s[2] = {m0, n0};

    auto issue = [&](int k0, int st) {
        #pragma unroll
        for (int i = 0; i < 8; i++) {
            int idx = i * 256 + tid;              // 0..2047
            int t = idx >> 10, rel = idx & 1023;
            int row = rel >> 3, c8 = (rel & 7) * 8;
            const __half* g = srcs[t] + (size_t)(r0s[t] + row) * EMB + k0 + c8;
            uint32_t s = sb + (uint32_t)(st * GSTG_H + t * GTILE_H + row * GP + c8) * 2;
            CP_ASYNC16(s, g);
        }
        CP_COMMIT();
    };

    issue(0, 0);
    float acc[4][4][4] = {};

    for (int c = 0; c < 16; c++) {
        const int st = c & 1;
        CP_WAIT0();
        __syncthreads();
        if (c + 1 < 16) issue((c + 1) * 64, st ^ 1);

        const uint32_t abase = sb + (uint32_t)(st * GSTG_H) * 2;
        const uint32_t bbase = sb + (uint32_t)(st * GSTG_H + GTILE_H) * 2;
        #pragma unroll
        for (int kc = 0; kc < 4; kc++) {
            uint32_t af[4][4], bf[2][4];
            #pragma unroll
            for (int mt = 0; mt < 4; mt++) {
                int row = wm * 64 + mt * 16 + (lane & 15);
                uint32_t a = abase + (row * GP + kc * 16 + 8 * (lane >> 4)) * 2;
                ldsm_x4(a, af[mt][0], af[mt][1], af[mt][2], af[mt][3]);
            }
            #pragma unroll
            for (int u = 0; u < 2; u++) {
                int row = wn * 32 + u * 16 + (lane & 7) + 8 * ((lane >> 3) & 1);
                uint32_t b = bbase + (row * GP + kc * 16 + 8 * (lane >> 4)) * 2;
                ldsm_x4(b, bf[u][0], bf[u][1], bf[u][2], bf[u][3]);
            }
            #pragma unroll
            for (int mt = 0; mt < 4; mt++)
                #pragma unroll
                for (int u = 0; u < 2; u++) {
                    mma_f16(acc[mt][2*u],   af[mt], bf[u][0], bf[u][2]);
                    mma_f16(acc[mt][2*u+1], af[mt], bf[u][1], bf[u][3]);
                }
        }
        __syncthreads();
    }

    #pragma unroll
    for (int mt = 0; mt < 4; mt++) {
        int grow = m0 + wm * 64 + mt * 16 + (lane >> 2);
        #pragma unroll
        for (int nt = 0; nt < 4; nt++) {
            int gcol = n0 + wn * 32 + nt * 8 + 2 * (lane & 3);
            float* a = acc[mt][nt];
            size_t o0 = (size_t)grow * EMB + gcol;
            size_t o1 = (size_t)(grow + 8) * EMB + gcol;
            if (Cf) {
                *(float2*)(Cf + o0) = make_float2(a[0], a[1]);
                *(float2*)(Cf + o1) = make_float2(a[2], a[3]);
            } else {
                __half* C1 = (z == 0) ? Q1 : (z == 1) ? K1 : V1;
                *(uint32_t*)(C1 + o0) = pack2h(a[0], a[1]);
                *(uint32_t*)(C1 + o1) = pack2h(a[2], a[3]);
            }
        }
    }
}

// ---------------------------------------------------------------------------
// Flash attention, single fp16 throughout: S = Q1@K1^T, O += P@V1.
// CTA = 128 q-rows, 8 warps x 16 rows, 64-key tiles, cp.async 2-stage,
// qt-descending remap, per-warp masked-tile skip.
// ---------------------------------------------------------------------------
#define FPH 72
#define FQ_H (128 * FPH)              // 9216 halves
#define FK_H (64 * FPH)               // 4608 halves
#define FSTG_H (2 * FK_H)             // K, V per stage
#define FLASH_SMEM ((FQ_H + 2 * FSTG_H) * 2 + 2 * 64 * 4)   // 56320 B

__global__ __launch_bounds__(256) void flash_tc(
    const __half* __restrict__ Q1, const __half* __restrict__ K1,
    const __half* __restrict__ V1,
    const int* __restrict__ am, __half* __restrict__ O1)
{
    extern __shared__ __half sm[];
    const uint32_t sb = smem_u32(sm);
    int* ambuf = (int*)(sm + FQ_H + 2 * FSTG_H);

    const int tid = threadIdx.x, lane = tid & 31, w = tid >> 5;
    const int qt = (int)(gridDim.x - 1 - blockIdx.x);   // heavy tiles first
    const int q0 = qt * 128;
    const size_t rowbase = (size_t)blockIdx.z * S_LEN;
    const int colbase = blockIdx.y * HD;

    const __half* srcs[2] = {K1, V1};

    auto prefetch = [&](int kt, int st) {
        const int k0 = kt * 64;
        #pragma unroll
        for (int i = 0; i < 4; i++) {
            int idx = i * 256 + tid;              // 0..1023
            int t = idx >> 9, j = idx & 511;
            int row = j >> 3, c8 = (j & 7) * 8;
            const __half* g = srcs[t] + (rowbase + k0 + row) * EMB + colbase + c8;
            uint32_t s = sb + (uint32_t)(FQ_H + st * FSTG_H + t * FK_H + row * FPH + c8) * 2;
            CP_ASYNC16(s, g);
        }
        if (tid < 16) {
            const int* g = am + rowbase + k0 + tid * 4;
            uint32_t s = sb + (uint32_t)(FQ_H + 2 * FSTG_H) * 2 + (st * 64 + tid * 4) * 4;
            CP_ASYNC16(s, g);
        }
        CP_COMMIT();
    };

    // Q tile (single)
    #pragma unroll
    for (int i = 0; i < 4; i++) {
        int idx = i * 256 + tid;
        int row = idx >> 3, c8 = (idx & 7) * 8;
        size_t go = (rowbase + q0 + row) * EMB + colbase + c8;
        *(float4*)&sm[row * FPH + c8] = *(const float4*)&Q1[go];
    }
    prefetch(0, 0);

    float oacc[8][4] = {};
    float mr0 = -1e30f, mr1 = -1e30f, lr0 = 0.f, lr1 = 0.f;

    const uint32_t aQ = sb;
    const int qrow  = q0 + w * 16 + (lane >> 2);
    const int qmaxw = q0 + w * 16 + 15;
    const int nkt = 2 * qt + 2;

    for (int kt = 0; kt < nkt; kt++) {
        const int k0 = kt * 64;
        const int st = kt & 1;
        CP_WAIT0();
        __syncthreads();
        if (kt + 1 < nkt) prefetch(kt + 1, st ^ 1);

        if (k0 > qmaxw) continue;   // fully masked for this warp

        const uint32_t aK = sb + (uint32_t)(FQ_H + st * FSTG_H) * 2;
        const uint32_t aV = aK + FK_H * 2;
        const int* amb = ambuf + st * 64;

        // ---- S = Q @ K^T (single term) ----
        float sacc[8][4] = {};
        #pragma unroll
        for (int kc = 0; kc < 4; kc++) {
            uint32_t qa[4];
            {
                int row = w * 16 + (lane & 15);
                uint32_t a = (row * FPH + kc * 16 + 8 * (lane >> 4)) * 2;
                ldsm_x4(aQ + a, qa[0], qa[1], qa[2], qa[3]);
            }
            #pragma unroll
            for (int np = 0; np < 4; np++) {
                int row = np * 16 + (lane & 7) + 8 * ((lane >> 3) & 1);
                uint32_t boff = (row * FPH + kc * 16 + 8 * (lane >> 4)) * 2;
                uint32_t kh[4];
                ldsm_x4(aK + boff, kh[0], kh[1], kh[2], kh[3]);
                mma_f16(sacc[2*np],   qa, kh[0], kh[2]);
                mma_f16(sacc[2*np+1], qa, kh[1], kh[3]);
            }
        }

        // ---- online softmax in fragments ----
        const bool needmask = (k0 + 63) > (q0 + w * 16);
        float mx0 = -1e30f, mx1 = -1e30f;
        #pragma unroll
        for (int t = 0; t < 8; t++) {
            int lc = t * 8 + 2 * (lane & 3);
            int a0 = amb[lc], a1 = amb[lc + 1];
            float s0 = a0 ? sacc[t][0] * 0.125f : -1e30f;
            float s1 = a1 ? sacc[t][1] * 0.125f : -1e30f;
            float s2 = a0 ? sacc[t][2] * 0.125f : -1e30f;
            float s3 = a1 ? sacc[t][3] * 0.125f : -1e30f;
            if (needmask) {
                int cg = k0 + lc;
                if (cg > qrow)         s0 = -1e30f;
                if (cg + 1 > qrow)     s1 = -1e30f;
                if (cg > qrow + 8)     s2 = -1e30f;
                if (cg + 1 > qrow + 8) s3 = -1e30f;
            }
            sacc[t][0] = s0; sacc[t][1] = s1; sacc[t][2] = s2; sacc[t][3] = s3;
            mx0 = fmaxf(mx0, fmaxf(s0, s1));
            mx1 = fmaxf(mx1, fmaxf(s2, s3));
        }
        mx0 = fmaxf(mx0, __shfl_xor_sync(0xffffffffu, mx0, 1));
        mx0 = fmaxf(mx0, __shfl_xor_sync(0xffffffffu, mx0, 2));
        mx1 = fmaxf(mx1, __shfl_xor_sync(0xffffffffu, mx1, 1));
        mx1 = fmaxf(mx1, __shfl_xor_sync(0xffffffffu, mx1, 2));
        float mn0 = fmaxf(mr0, mx0), mn1 = fmaxf(mr1, mx1);
        float al0 = __expf(mr0 - mn0), al1 = __expf(mr1 - mn1);
        mr0 = mn0; mr1 = mn1;
        float sm0 = 0.f, sm1 = 0.f;
        #pragma unroll
        for (int t = 0; t < 8; t++) {
            float p0 = __expf(sacc[t][0] - mn0);
            float p1 = __expf(sacc[t][1] - mn0);
            float p2 = __expf(sacc[t][2] - mn1);
            float p3 = __expf(sacc[t][3] - mn1);
            sacc[t][0] = p0; sacc[t][1] = p1; sacc[t][2] = p2; sacc[t][3] = p3;
            sm0 += p0 + p1; sm1 += p2 + p3;
        }
        sm0 += __shfl_xor_sync(0xffffffffu, sm0, 1);
        sm0 += __shfl_xor_sync(0xffffffffu, sm0, 2);
        sm1 += __shfl_xor_sync(0xffffffffu, sm1, 1);
        sm1 += __shfl_xor_sync(0xffffffffu, sm1, 2);
        lr0 = lr0 * al0 + sm0;
        lr1 = lr1 * al1 + sm1;
        #pragma unroll
        for (int t = 0; t < 8; t++) {
            oacc[t][0] *= al0; oacc[t][1] *= al0;
            oacc[t][2] *= al1; oacc[t][3] *= al1;
        }

        // ---- O += P @ V (single term) ----
        #pragma unroll
        for (int t = 0; t < 4; t++) {
            uint32_t ph[4];
            ph[0] = pack2h(sacc[2*t][0],   sacc[2*t][1]);
            ph[1] = pack2h(sacc[2*t][2],   sacc[2*t][3]);
            ph[2] = pack2h(sacc[2*t+1][0], sacc[2*t+1][1]);
            ph[3] = pack2h(sacc[2*t+1][2], sacc[2*t+1][3]);
            #pragma unroll
            for (int u = 0; u < 4; u++) {
                int row = t * 16 + (lane & 7) + 8 * ((lane >> 3) & 1);
                int coln = u * 16 + 8 * (lane >> 4);
                uint32_t boff = (row * FPH + coln) * 2;
                uint32_t vh[4];
                ldsm_x4t(aV + boff, vh[0], vh[1], vh[2], vh[3]);
                mma_f16(oacc[2*u],   ph, vh[0], vh[1]);
                mma_f16(oacc[2*u+1], ph, vh[2], vh[3]);
            }
        }
    }

    // ---- epilogue: O /= l, single fp16 ----
    float i0 = 1.f / lr0, i1 = 1.f / lr1;
    #pragma unroll
    for (int t = 0; t < 8; t++) {
        int col = colbase + t * 8 + 2 * (lane & 3);
        size_t o0 = (rowbase + q0 + w * 16 + (lane >> 2)) * EMB + col;
        size_t o1 = o0 + 8 * EMB;
        *(uint32_t*)(O1 + o0) = pack2h(oacc[t][0] * i0, oacc[t][1] * i0);
        *(uint32_t*)(O1 + o1) = pack2h(oacc[t][2] * i1, oacc[t][3] * i1);
    }
}

// ---------------------------------------------------------------------------
extern "C" void kernel_launch(void* const* d_in, const int* in_sizes, int n_in,
                              void* d_out, int out_size)
{
    const float* x  = (const float*)d_in[0];
    const int*   am = (const int*)d_in[1];
    const float* w[4] = { (const float*)d_in[2], (const float*)d_in[3],
                          (const float*)d_in[4], (const float*)d_in[5] };
    float* out = (float*)d_out;

    __half *x1, *wp, *Q1, *K1, *V1, *O1;
    cudaGetSymbolAddress((void**)&x1, g_x1);
    cudaGetSymbolAddress((void**)&wp, g_w);
    cudaGetSymbolAddress((void**)&Q1, g_Q1);
    cudaGetSymbolAddress((void**)&K1, g_K1);
    cudaGetSymbolAddress((void**)&V1, g_V1);
    cudaGetSymbolAddress((void**)&O1, g_O1);

    cudaFuncSetAttribute(gemm_tc, cudaFuncAttributeMaxDynamicSharedMemorySize, GEMM_SMEM);
    cudaFuncSetAttribute(flash_tc, cudaFuncAttributeMaxDynamicSharedMemorySize, FLASH_SMEM);

    cvt_k<<<(NTOK * EMB / 4 + 255) / 256, 256>>>(x, x1, NTOK * EMB / 4);
    cvt_w4<<<(4 * EMB * EMB / 4 + 255) / 256, 256>>>(w[0], w[1], w[2], w[3], wp);

    // fused Q/K/V projections (blockIdx.z selects weight + destination)
    gemm_tc<<<dim3(EMB / 128, NTOK / 128, 3), 256, GEMM_SMEM>>>(
        x1, wp, nullptr, Q1, K1, V1);

    flash_tc<<<dim3(S_LEN / 128, NH, BATCH), 256, FLASH_SMEM>>>(
        Q1, K1, V1, am, O1);

    // output projection -> fp32
    gemm_tc<<<dim3(EMB / 128, NTOK / 128, 1), 256, GEMM_SMEM>>>(
        O1, wp + 3 * (size_t)EMB * EMB, out, nullptr, nullptr, nullptr);
}

// round 15
// speedup vs baseline: 2.7833x; 1.0596x over previous
#include <cuda_runtime.h>
#include <cuda_fp16.h>
#include <cstdint>
#include <math.h>

#define S_LEN 2048
#define BATCH 4
#define EMB   1024
#define NH    16
#define HD    64
#define NTOK  (BATCH * S_LEN)   // 8192

// ---------------- scratch (device globals; no allocs allowed) --------------
__device__ __half g_x1[NTOK * EMB];
__device__ __half g_w[4][EMB * EMB];
__device__ __half g_Q1[NTOK * EMB];
__device__ __half g_K1[NTOK * EMB];
__device__ __half g_V1[NTOK * EMB];
__device__ __half g_O1[NTOK * EMB];

// ---------------- helpers --------------------------------------------------
__device__ __forceinline__ uint32_t smem_u32(const void* p) {
    uint32_t a;
    asm("{ .reg .u64 t; cvta.to.shared.u64 t, %1; cvt.u32.u64 %0, t; }" : "=r"(a) : "l"(p));
    return a;
}
__device__ __forceinline__ void ldsm_x4(uint32_t a, uint32_t& r0, uint32_t& r1,
                                        uint32_t& r2, uint32_t& r3) {
    asm volatile("ldmatrix.sync.aligned.m8n8.x4.shared.b16 {%0,%1,%2,%3}, [%4];"
                 : "=r"(r0), "=r"(r1), "=r"(r2), "=r"(r3) : "r"(a));
}
__device__ __forceinline__ void ldsm_x4t(uint32_t a, uint32_t& r0, uint32_t& r1,
                                         uint32_t& r2, uint32_t& r3) {
    asm volatile("ldmatrix.sync.aligned.m8n8.x4.trans.shared.b16 {%0,%1,%2,%3}, [%4];"
                 : "=r"(r0), "=r"(r1), "=r"(r2), "=r"(r3) : "r"(a));
}
__device__ __forceinline__ void mma_f16(float* d, const uint32_t* a,
                                        uint32_t b0, uint32_t b1) {
    asm volatile(
        "mma.sync.aligned.m16n8k16.row.col.f32.f16.f16.f32 "
        "{%0,%1,%2,%3}, {%4,%5,%6,%7}, {%8,%9}, {%0,%1,%2,%3};"
        : "+f"(d[0]), "+f"(d[1]), "+f"(d[2]), "+f"(d[3])
        : "r"(a[0]), "r"(a[1]), "r"(a[2]), "r"(a[3]), "r"(b0), "r"(b1));
}
__device__ __forceinline__ uint32_t pack2h(float x, float y) {
    __half2 h = __floats2half2_rn(x, y);
    return *(uint32_t*)&h;
}
#define CP_ASYNC16(s, g) \
    asm volatile("cp.async.cg.shared.global [%0], [%1], 16;" :: "r"(s), "l"(g) : "memory")
#define CP_COMMIT() asm volatile("cp.async.commit_group;" ::: "memory")
#define CP_WAIT0()  asm volatile("cp.async.wait_group 0;" ::: "memory")

// ---------------------------------------------------------------------------
// fp32 -> fp16 converts
// ---------------------------------------------------------------------------
__global__ __launch_bounds__(256) void cvt_k(
    const float* __restrict__ src, __half* __restrict__ dst, int n4)
{
    int i = blockIdx.x * 256 + threadIdx.x;
    if (i >= n4) return;
    float4 v = ((const float4*)src)[i];
    __half h[4] = { __float2half_rn(v.x), __float2half_rn(v.y),
                    __float2half_rn(v.z), __float2half_rn(v.w) };
    ((uint2*)dst)[i] = *(uint2*)h;
}

__global__ __launch_bounds__(256) void cvt_w4(
    const float* __restrict__ w0, const float* __restrict__ w1,
    const float* __restrict__ w2, const float* __restrict__ w3,
    __half* __restrict__ dst)
{
    const int per = EMB * EMB / 4;
    int i = blockIdx.x * 256 + threadIdx.x;
    int z = i / per, j = i % per;
    if (z >= 4) return;
    const float* src = (z == 0) ? w0 : (z == 1) ? w1 : (z == 2) ? w2 : w3;
    float4 v = ((const float4*)src)[j];
    __half h[4] = { __float2half_rn(v.x), __float2half_rn(v.y),
                    __float2half_rn(v.z), __float2half_rn(v.w) };
    ((uint2*)dst)[i] = *(uint2*)h;
}

// ---------------------------------------------------------------------------
// mma.sync fp16 GEMM (single-term): C = A1 @ W_z^T.  (unchanged — at ceiling)
// ---------------------------------------------------------------------------
#define GP 72
#define GTILE_H (128 * GP)
#define GSTG_H  (2 * GTILE_H)
#define GEMM_SMEM (2 * GSTG_H * 2)

__global__ __launch_bounds__(256) void gemm_tc(
    const __half* __restrict__ A1, const __half* __restrict__ Wbase,
    float* __restrict__ Cf,
    __half* __restrict__ Q1, __half* __restrict__ K1, __half* __restrict__ V1)
{
    extern __shared__ __half sm[];
    const uint32_t sb = smem_u32(sm);
    const int tid = threadIdx.x, lane = tid & 31, w = tid >> 5;
    const int wm = w & 1, wn = w >> 1;
    const int m0 = blockIdx.y * 128, n0 = blockIdx.x * 128;
    const int z = blockIdx.z;
    const __half* B = Wbase + (size_t)z * EMB * EMB;

    const __half* srcs[2] = {A1, B};
    const int r0s[2] = {m0, n0};

    auto issue = [&](int k0, int st) {
        #pragma unroll
        for (int i = 0; i < 8; i++) {
            int idx = i * 256 + tid;
            int t = idx >> 10, rel = idx & 1023;
            int row = rel >> 3, c8 = (rel & 7) * 8;
            const __half* g = srcs[t] + (size_t)(r0s[t] + row) * EMB + k0 + c8;
            uint32_t s = sb + (uint32_t)(st * GSTG_H + t * GTILE_H + row * GP + c8) * 2;
            CP_ASYNC16(s, g);
        }
        CP_COMMIT();
    };

    issue(0, 0);
    float acc[4][4][4] = {};

    for (int c = 0; c < 16; c++) {
        const int st = c & 1;
        CP_WAIT0();
        __syncthreads();
        if (c + 1 < 16) issue((c + 1) * 64, st ^ 1);

        const uint32_t abase = sb + (uint32_t)(st * GSTG_H) * 2;
        const uint32_t bbase = sb + (uint32_t)(st * GSTG_H + GTILE_H) * 2;
        #pragma unroll
        for (int kc = 0; kc < 4; kc++) {
            uint32_t af[4][4], bf[2][4];
            #pragma unroll
            for (int mt = 0; mt < 4; mt++) {
                int row = wm * 64 + mt * 16 + (lane & 15);
                uint32_t a = abase + (row * GP + kc * 16 + 8 * (lane >> 4)) * 2;
                ldsm_x4(a, af[mt][0], af[mt][1], af[mt][2], af[mt][3]);
            }
            #pragma unroll
            for (int u = 0; u < 2; u++) {
                int row = wn * 32 + u * 16 + (lane & 7) + 8 * ((lane >> 3) & 1);
                uint32_t b = bbase + (row * GP + kc * 16 + 8 * (lane >> 4)) * 2;
                ldsm_x4(b, bf[u][0], bf[u][1], bf[u][2], bf[u][3]);
            }
            #pragma unroll
            for (int mt = 0; mt < 4; mt++)
                #pragma unroll
                for (int u = 0; u < 2; u++) {
                    mma_f16(acc[mt][2*u],   af[mt], bf[u][0], bf[u][2]);
                    mma_f16(acc[mt][2*u+1], af[mt], bf[u][1], bf[u][3]);
                }
        }
        __syncthreads();
    }

    #pragma unroll
    for (int mt = 0; mt < 4; mt++) {
        int grow = m0 + wm * 64 + mt * 16 + (lane >> 2);
        #pragma unroll
        for (int nt = 0; nt < 4; nt++) {
            int gcol = n0 + wn * 32 + nt * 8 + 2 * (lane & 3);
            float* a = acc[mt][nt];
            size_t o0 = (size_t)grow * EMB + gcol;
            size_t o1 = (size_t)(grow + 8) * EMB + gcol;
            if (Cf) {
                *(float2*)(Cf + o0) = make_float2(a[0], a[1]);
                *(float2*)(Cf + o1) = make_float2(a[2], a[3]);
            } else {
                __half* C1 = (z == 0) ? Q1 : (z == 1) ? K1 : V1;
                *(uint32_t*)(C1 + o0) = pack2h(a[0], a[1]);
                *(uint32_t*)(C1 + o1) = pack2h(a[2], a[3]);
            }
        }
    }
}

// ---------------------------------------------------------------------------
// Flash attention, single fp16, exp2-domain softmax, per-tile mask fast path.
// CTA = 128 q-rows, 8 warps x 16 rows, 64-key tiles, cp.async 2-stage.
// ---------------------------------------------------------------------------
#define FPH 72
#define FQ_H (128 * FPH)
#define FK_H (64 * FPH)
#define FSTG_H (2 * FK_H)
#define FLASH_SMEM ((FQ_H + 2 * FSTG_H) * 2 + 2 * 64 * 4 + 16)
#define C2SCL 0.180336880f   /* 0.125 * log2(e) */

__global__ __launch_bounds__(256) void flash_tc(
    const __half* __restrict__ Q1, const __half* __restrict__ K1,
    const __half* __restrict__ V1,
    const int* __restrict__ am, __half* __restrict__ O1)
{
    extern __shared__ __half sm[];
    const uint32_t sb = smem_u32(sm);
    float* maddbuf = (float*)(sm + FQ_H + 2 * FSTG_H);   // 2 x 64 floats
    int*   flagbuf = (int*)(maddbuf + 2 * 64);           // 2 x 2 ints

    const int tid = threadIdx.x, lane = tid & 31, w = tid >> 5;
    const int qt = (int)(gridDim.x - 1 - blockIdx.x);
    const int q0 = qt * 128;
    const size_t rowbase = (size_t)blockIdx.z * S_LEN;
    const int colbase = blockIdx.y * HD;

    const __half* srcs[2] = {K1, V1};

    auto prefetch = [&](int kt, int st) {
        const int k0 = kt * 64;
        #pragma unroll
        for (int i = 0; i < 4; i++) {
            int idx = i * 256 + tid;
            int t = idx >> 9, j = idx & 511;
            int row = j >> 3, c8 = (j & 7) * 8;
            const __half* g = srcs[t] + (rowbase + k0 + row) * EMB + colbase + c8;
            uint32_t s = sb + (uint32_t)(FQ_H + st * FSTG_H + t * FK_H + row * FPH + c8) * 2;
            CP_ASYNC16(s, g);
        }
        CP_COMMIT();
        if (tid < 64) {
            int v = am[rowbase + k0 + tid];
            maddbuf[st * 64 + tid] = v ? 0.f : -1e30f;
            unsigned ok = __all_sync(0xffffffffu, v != 0);
            if ((tid & 31) == 0) flagbuf[st * 2 + (tid >> 5)] = (int)ok;
        }
    };

    // Q tile
    #pragma unroll
    for (int i = 0; i < 4; i++) {
        int idx = i * 256 + tid;
        int row = idx >> 3, c8 = (idx & 7) * 8;
        size_t go = (rowbase + q0 + row) * EMB + colbase + c8;
        *(float4*)&sm[row * FPH + c8] = *(const float4*)&Q1[go];
    }
    prefetch(0, 0);

    float oacc[8][4] = {};
    float mr0 = -1e30f, mr1 = -1e30f, lr0 = 0.f, lr1 = 0.f;

    const uint32_t aQ = sb;
    const int qrow  = q0 + w * 16 + (lane >> 2);
    const int qmaxw = q0 + w * 16 + 15;
    const int nkt = 2 * qt + 2;

    for (int kt = 0; kt < nkt; kt++) {
        const int k0 = kt * 64;
        const int st = kt & 1;
        CP_WAIT0();
        __syncthreads();
        if (kt + 1 < nkt) prefetch(kt + 1, st ^ 1);

        if (k0 > qmaxw) continue;

        const uint32_t aK = sb + (uint32_t)(FQ_H + st * FSTG_H) * 2;
        const uint32_t aV = aK + FK_H * 2;

        // ---- S = Q @ K^T ----
        float sacc[8][4] = {};
        #pragma unroll
        for (int kc = 0; kc < 4; kc++) {
            uint32_t qa[4];
            {
                int row = w * 16 + (lane & 15);
                uint32_t a = (row * FPH + kc * 16 + 8 * (lane >> 4)) * 2;
                ldsm_x4(aQ + a, qa[0], qa[1], qa[2], qa[3]);
            }
            #pragma unroll
            for (int np = 0; np < 4; np++) {
                int row = np * 16 + (lane & 7) + 8 * ((lane >> 3) & 1);
                uint32_t boff = (row * FPH + kc * 16 + 8 * (lane >> 4)) * 2;
                uint32_t kh[4];
                ldsm_x4(aK + boff, kh[0], kh[1], kh[2], kh[3]);
                mma_f16(sacc[2*np],   qa, kh[0], kh[2]);
                mma_f16(sacc[2*np+1], qa, kh[1], kh[3]);
            }
        }

        // ---- scale + mask (exp2 domain) ----
        const bool needmask = (k0 + 63) > (q0 + w * 16);
        const bool allv = flagbuf[st * 2] && flagbuf[st * 2 + 1];
        float mx0 = -1e30f, mx1 = -1e30f;
        if (allv && !needmask) {
            // fast path: no pad mask, no causal mask
            #pragma unroll
            for (int t = 0; t < 8; t++) {
                float s0 = sacc[t][0] * C2SCL;
                float s1 = sacc[t][1] * C2SCL;
                float s2 = sacc[t][2] * C2SCL;
                float s3 = sacc[t][3] * C2SCL;
                sacc[t][0] = s0; sacc[t][1] = s1; sacc[t][2] = s2; sacc[t][3] = s3;
                mx0 = fmaxf(mx0, fmaxf(s0, s1));
                mx1 = fmaxf(mx1, fmaxf(s2, s3));
            }
        } else {
            const float* mad = maddbuf + st * 64;
            #pragma unroll
            for (int t = 0; t < 8; t++) {
                int lc = t * 8 + 2 * (lane & 3);
                float m0v = mad[lc], m1v = mad[lc + 1];
                float s0 = fmaf(sacc[t][0], C2SCL, m0v);
                float s1 = fmaf(sacc[t][1], C2SCL, m1v);
                float s2 = fmaf(sacc[t][2], C2SCL, m0v);
                float s3 = fmaf(sacc[t][3], C2SCL, m1v);
                if (needmask) {
                    int cg = k0 + lc;
                    if (cg > qrow)         s0 = -1e30f;
                    if (cg + 1 > qrow)     s1 = -1e30f;
                    if (cg > qrow + 8)     s2 = -1e30f;
                    if (cg + 1 > qrow + 8) s3 = -1e30f;
                }
                sacc[t][0] = s0; sacc[t][1] = s1; sacc[t][2] = s2; sacc[t][3] = s3;
                mx0 = fmaxf(mx0, fmaxf(s0, s1));
                mx1 = fmaxf(mx1, fmaxf(s2, s3));
            }
        }
        mx0 = fmaxf(mx0, __shfl_xor_sync(0xffffffffu, mx0, 1));
        mx0 = fmaxf(mx0, __shfl_xor_sync(0xffffffffu, mx0, 2));
        mx1 = fmaxf(mx1, __shfl_xor_sync(0xffffffffu, mx1, 1));
        mx1 = fmaxf(mx1, __shfl_xor_sync(0xffffffffu, mx1, 2));
        float mn0 = fmaxf(mr0, mx0), mn1 = fmaxf(mr1, mx1);
        float al0 = exp2f(mr0 - mn0), al1 = exp2f(mr1 - mn1);
        mr0 = mn0; mr1 = mn1;
        float sm0 = 0.f, sm1 = 0.f;
        #pragma unroll
        for (int t = 0; t < 8; t++) {
            float p0 = exp2f(sacc[t][0] - mn0);
            float p1 = exp2f(sacc[t][1] - mn0);
            float p2 = exp2f(sacc[t][2] - mn1);
            float p3 = exp2f(sacc[t][3] - mn1);
            sacc[t][0] = p0; sacc[t][1] = p1; sacc[t][2] = p2; sacc[t][3] = p3;
            sm0 += p0 + p1; sm1 += p2 + p3;
        }
        sm0 += __shfl_xor_sync(0xffffffffu, sm0, 1);
        sm0 += __shfl_xor_sync(0xffffffffu, sm0, 2);
        sm1 += __shfl_xor_sync(0xffffffffu, sm1, 1);
        sm1 += __shfl_xor_sync(0xffffffffu, sm1, 2);
        lr0 = lr0 * al0 + sm0;
        lr1 = lr1 * al1 + sm1;
        #pragma unroll
        for (int t = 0; t < 8; t++) {
            oacc[t][0] *= al0; oacc[t][1] *= al0;
            oacc[t][2] *= al1; oacc[t][3] *= al1;
        }

        // ---- O += P @ V ----
        #pragma unroll
        for (int t = 0; t < 4; t++) {
            uint32_t ph[4];
            ph[0] = pack2h(sacc[2*t][0],   sacc[2*t][1]);
            ph[1] = pack2h(sacc[2*t][2],   sacc[2*t][3]);
            ph[2] = pack2h(sacc[2*t+1][0], sacc[2*t+1][1]);
            ph[3] = pack2h(sacc[2*t+1][2], sacc[2*t+1][3]);
            #pragma unroll
            for (int u = 0; u < 4; u++) {
                int row = t * 16 + (lane & 7) + 8 * ((lane >> 3) & 1);
                int coln = u * 16 + 8 * (lane >> 4);
                uint32_t boff = (row * FPH + coln) * 2;
                uint32_t vh[4];
                ldsm_x4t(aV + boff, vh[0], vh[1], vh[2], vh[3]);
                mma_f16(oacc[2*u],   ph, vh[0], vh[1]);
                mma_f16(oacc[2*u+1], ph, vh[2], vh[3]);
            }
        }
    }

    // ---- epilogue ----
    float i0 = 1.f / lr0, i1 = 1.f / lr1;
    #pragma unroll
    for (int t = 0; t < 8; t++) {
        int col = colbase + t * 8 + 2 * (lane & 3);
        size_t o0 = (rowbase + q0 + w * 16 + (lane >> 2)) * EMB + col;
        size_t o1 = o0 + 8 * EMB;
        *(uint32_t*)(O1 + o0) = pack2h(oacc[t][0] * i0, oacc[t][1] * i0);
        *(uint32_t*)(O1 + o1) = pack2h(oacc[t][2] * i1, oacc[t][3] * i1);
    }
}

// ---------------------------------------------------------------------------
extern "C" void kernel_launch(void* const* d_in, const int* in_sizes, int n_in,
                              void* d_out, int out_size)
{
    const float* x  = (const float*)d_in[0];
    const int*   am = (const int*)d_in[1];
    const float* w[4] = { (const float*)d_in[2], (const float*)d_in[3],
                          (const float*)d_in[4], (const float*)d_in[5] };
    float* out = (float*)d_out;

    __half *x1, *wp, *Q1, *K1, *V1, *O1;
    cudaGetSymbolAddress((void**)&x1, g_x1);
    cudaGetSymbolAddress((void**)&wp, g_w);
    cudaGetSymbolAddress((void**)&Q1, g_Q1);
    cudaGetSymbolAddress((void**)&K1, g_K1);
    cudaGetSymbolAddress((void**)&V1, g_V1);
    cudaGetSymbolAddress((void**)&O1, g_O1);

    cudaFuncSetAttribute(gemm_tc, cudaFuncAttributeMaxDynamicSharedMemorySize, GEMM_SMEM);
    cudaFuncSetAttribute(flash_tc, cudaFuncAttributeMaxDynamicSharedMemorySize, FLASH_SMEM);

    cvt_k<<<(NTOK * EMB / 4 + 255) / 256, 256>>>(x, x1, NTOK * EMB / 4);
    cvt_w4<<<(4 * EMB * EMB / 4 + 255) / 256, 256>>>(w[0], w[1], w[2], w[3], wp);

    gemm_tc<<<dim3(EMB / 128, NTOK / 128, 3), 256, GEMM_SMEM>>>(
        x1, wp, nullptr, Q1, K1, V1);

    flash_tc<<<dim3(S_LEN / 128, NH, BATCH), 256, FLASH_SMEM>>>(
        Q1, K1, V1, am, O1);

    gemm_tc<<<dim3(EMB / 128, NTOK / 128, 1), 256, GEMM_SMEM>>>(
        O1, wp + 3 * (size_t)EMB * EMB, out, nullptr, nullptr, nullptr);
}